// round 8
// baseline (speedup 1.0000x reference)
#include <cuda_runtime.h>
#include <cuda_bf16.h>
#include <math.h>
#include <stdint.h>

#define BB 2
#define SS 2048
#define DD 2048
#define NH 32
#define NKV 8
#define HD 64
#define KVD (NKV*HD)   /* 512 */
#define BS (BB*SS)     /* 4096 */

// fp32 scratch (GEMM outputs)
__device__ float g_Q[BS*DD];
__device__ float g_K[BS*KVD];
__device__ float g_V[BS*KVD];

// bf16 hi/lo split scratch
__device__ __nv_bfloat16 g_xh[BS*DD],  g_xl[BS*DD];
__device__ __nv_bfloat16 g_Ah[BS*DD],  g_Al[BS*DD];
__device__ __nv_bfloat16 g_Qh[BS*DD],  g_Ql[BS*DD];
__device__ __nv_bfloat16 g_Kh[BS*KVD], g_Kl[BS*KVD];
__device__ __nv_bfloat16 g_Vh[BS*KVD], g_Vl[BS*KVD];
// transposed weight splits [N x K]
__device__ __nv_bfloat16 g_wqTh[DD*DD],  g_wqTl[DD*DD];
__device__ __nv_bfloat16 g_wkTh[KVD*DD], g_wkTl[KVD*DD];
__device__ __nv_bfloat16 g_wvTh[KVD*DD], g_wvTl[KVD*DD];
__device__ __nv_bfloat16 g_woTh[DD*DD],  g_woTl[DD*DD];

// ---------------------------------------------------------------------------
// helpers
// ---------------------------------------------------------------------------
__device__ __forceinline__ uint32_t smem_u32(const void* p) {
    uint32_t a;
    asm("{ .reg .u64 t; cvta.to.shared.u64 t, %1; cvt.u32.u64 %0, t; }"
        : "=r"(a) : "l"(p));
    return a;
}

__device__ __forceinline__ unsigned pkbf(__nv_bfloat16 a, __nv_bfloat16 b)
{
    return (unsigned)__bfloat16_as_ushort(a) | ((unsigned)__bfloat16_as_ushort(b) << 16);
}

__device__ __forceinline__ void mma_bf16(float* c, const unsigned* a, const unsigned* b)
{
    asm volatile(
        "mma.sync.aligned.m16n8k16.row.col.f32.bf16.bf16.f32 "
        "{%0,%1,%2,%3}, {%4,%5,%6,%7}, {%8,%9}, {%0,%1,%2,%3};\n"
        : "+f"(c[0]), "+f"(c[1]), "+f"(c[2]), "+f"(c[3])
        : "r"(a[0]), "r"(a[1]), "r"(a[2]), "r"(a[3]), "r"(b[0]), "r"(b[1]));
}

__device__ __forceinline__ void ldmx4(unsigned* r, const __nv_bfloat16* p)
{
    unsigned a = smem_u32(p);
    asm volatile("ldmatrix.sync.aligned.m8n8.x4.shared.b16 {%0,%1,%2,%3}, [%4];"
                 : "=r"(r[0]), "=r"(r[1]), "=r"(r[2]), "=r"(r[3]) : "r"(a));
}
__device__ __forceinline__ void ldmx4t(unsigned* r, const __nv_bfloat16* p)
{
    unsigned a = smem_u32(p);
    asm volatile("ldmatrix.sync.aligned.m8n8.x4.trans.shared.b16 {%0,%1,%2,%3}, [%4];"
                 : "=r"(r[0]), "=r"(r[1]), "=r"(r[2]), "=r"(r[3]) : "r"(a));
}

// ---------------------------------------------------------------------------
// fp32 -> (hi, lo) bf16 split. dsel: 0 = x -> g_xh/g_xl, 1 = g_V -> g_Vh/g_Vl
// ---------------------------------------------------------------------------
__global__ void cvt_kernel(const float* srcExt, int dsel, int n)
{
    int i = blockIdx.x * blockDim.x + threadIdx.x;
    if (i >= n) return;
    const float* src = (dsel == 1) ? g_V : srcExt;
    float v = src[i];
    __nv_bfloat16 hi = __float2bfloat16(v);
    __nv_bfloat16 lo = __float2bfloat16(v - __bfloat162float(hi));
    __nv_bfloat16* ph = (dsel == 1) ? g_Vh : g_xh;
    __nv_bfloat16* pl = (dsel == 1) ? g_Vl : g_xl;
    ph[i] = hi; pl[i] = lo;
}

// ---------------------------------------------------------------------------
// Weight transpose + split: w [K,N] fp32 -> wT hi/lo [N,K] bf16.
// ---------------------------------------------------------------------------
__global__ void wtr_kernel(const float* __restrict__ w, int dsel, int K, int N)
{
    __shared__ float t[32][33];
    __nv_bfloat16 *ph, *pl;
    switch (dsel) {
        case 0: ph = g_wqTh; pl = g_wqTl; break;
        case 1: ph = g_wkTh; pl = g_wkTl; break;
        case 2: ph = g_wvTh; pl = g_wvTl; break;
        default:ph = g_woTh; pl = g_woTl; break;
    }
    int n0 = blockIdx.x * 32, k0 = blockIdx.y * 32;
    int tx = threadIdx.x, ty = threadIdx.y;
#pragma unroll
    for (int yy = 0; yy < 4; yy++) {
        int k = k0 + ty + yy * 8;
        t[ty + yy * 8][tx] = w[(size_t)k * N + n0 + tx];
    }
    __syncthreads();
#pragma unroll
    for (int yy = 0; yy < 4; yy++) {
        int n = n0 + ty + yy * 8;
        float v = t[tx][ty + yy * 8];
        __nv_bfloat16 hi = __float2bfloat16(v);
        __nv_bfloat16 lo = __float2bfloat16(v - __bfloat162float(hi));
        ph[(size_t)n * K + k0 + tx] = hi;
        pl[(size_t)n * K + k0 + tx] = lo;
    }
}

// ---------------------------------------------------------------------------
// bf16-split GEMM: 128x128 CTA tile, 4 warps, warp tile 64x64, BK=32,
// cp.async double buffer. C[M,N] = A[M,K] @ B^T (B stored [N,K]).
// ---------------------------------------------------------------------------
#define GSTR 40                       /* padded row stride (bf16 elems) */
#define GMAT (128*GSTR*2)             /* bytes per matrix buffer: 10240 */
#define GSTAGE (4*GMAT)               /* 40960 */
#define GEMM_SMEM (2*GSTAGE)          /* 81920 */

__global__ __launch_bounds__(128) void gemm_mma(int asel, int bsel,
                                                float* Cext, int csel,
                                                int M, int N, int K)
{
    extern __shared__ char dsm[];

    const __nv_bfloat16* Ah = asel ? g_Ah : g_xh;
    const __nv_bfloat16* Al = asel ? g_Al : g_xl;
    const __nv_bfloat16 *Bh, *Bl;
    switch (bsel) {
        case 0:  Bh = g_wqTh; Bl = g_wqTl; break;
        case 1:  Bh = g_wkTh; Bl = g_wkTl; break;
        case 2:  Bh = g_wvTh; Bl = g_wvTl; break;
        default: Bh = g_woTh; Bl = g_woTl; break;
    }
    float* C = (csel == 0) ? g_Q : (csel == 1) ? g_K : (csel == 2) ? g_V : Cext;

    const int tid  = threadIdx.x;
    const int lane = tid & 31;
    const int wid  = tid >> 5;          // 0..3
    const int g    = lane >> 2;
    const int tg   = lane & 3;
    const int warpM = (wid >> 1) * 64;
    const int warpN = (wid & 1) * 64;
    const int bm = blockIdx.y * 128;
    const int bn = blockIdx.x * 128;

    const __nv_bfloat16* srcs[4] = {Ah, Al, Bh, Bl};

    float acc[4][8][4];
#pragma unroll
    for (int a = 0; a < 4; a++)
#pragma unroll
        for (int b = 0; b < 8; b++)
#pragma unroll
            for (int c = 0; c < 4; c++) acc[a][b][c] = 0.f;

    auto docopy = [&](int ch) {
        const uint32_t sb = smem_u32(dsm) + (ch & 1) * GSTAGE;
#pragma unroll
        for (int it = 0; it < 16; it++) {
            int o = tid + it * 128;
            int mat = o >> 9;
            int idx = o & 511;
            int r = idx >> 2, c8 = (idx & 3) * 8;
            int rowbase = (mat < 2) ? bm : bn;
            uint32_t so = sb + mat * GMAT + r * (GSTR * 2) + c8 * 2;
            const __nv_bfloat16* gp = srcs[mat] + (size_t)(rowbase + r) * K + ch * 32 + c8;
            asm volatile("cp.async.cg.shared.global [%0], [%1], 16;\n"
                         :: "r"(so), "l"(gp));
        }
        asm volatile("cp.async.commit_group;\n");
    };

    const int nkb = K / 32;
    docopy(0);

    for (int kb = 0; kb < nkb; kb++) {
        if (kb + 1 < nkb) {
            docopy(kb + 1);
            asm volatile("cp.async.wait_group 1;\n" ::: "memory");
        } else {
            asm volatile("cp.async.wait_group 0;\n" ::: "memory");
        }
        __syncthreads();

        const __nv_bfloat16* sAh = (const __nv_bfloat16*)(dsm + (kb & 1) * GSTAGE);
        const __nv_bfloat16* sAl = sAh + 128 * GSTR;
        const __nv_bfloat16* sBh = sAl + 128 * GSTR;
        const __nv_bfloat16* sBl = sBh + 128 * GSTR;

#pragma unroll
        for (int ks = 0; ks < 2; ks++) {
            const int kc = ks * 16;
            unsigned ah[4][4], al[4][4];
            {
                int arow = warpM + (lane & 15);
                int acol = kc + (lane >> 4) * 8;
#pragma unroll
                for (int mt = 0; mt < 4; mt++) {
                    ldmx4(ah[mt], &sAh[(arow + mt * 16) * GSTR + acol]);
                    ldmx4(al[mt], &sAl[(arow + mt * 16) * GSTR + acol]);
                }
            }
            unsigned bh[4][4], bl[4][4];
            {
                int brow = (lane & 7) + ((lane >> 4) & 1) * 8;
                int bcol = kc + ((lane >> 3) & 1) * 8;
#pragma unroll
                for (int ng = 0; ng < 4; ng++) {
                    ldmx4(bh[ng], &sBh[(warpN + ng * 16 + brow) * GSTR + bcol]);
                    ldmx4(bl[ng], &sBl[(warpN + ng * 16 + brow) * GSTR + bcol]);
                }
            }
#pragma unroll
            for (int mt = 0; mt < 4; mt++)
#pragma unroll
                for (int ng = 0; ng < 4; ng++) {
                    mma_bf16(acc[mt][2 * ng],     ah[mt], bh[ng]);
                    mma_bf16(acc[mt][2 * ng],     ah[mt], bl[ng]);
                    mma_bf16(acc[mt][2 * ng],     al[mt], bh[ng]);
                    mma_bf16(acc[mt][2 * ng + 1], ah[mt], bh[ng] + 2);
                    mma_bf16(acc[mt][2 * ng + 1], ah[mt], bl[ng] + 2);
                    mma_bf16(acc[mt][2 * ng + 1], al[mt], bh[ng] + 2);
                }
        }
        __syncthreads();
    }

#pragma unroll
    for (int mt = 0; mt < 4; mt++)
#pragma unroll
        for (int nt = 0; nt < 8; nt++) {
            int row = bm + warpM + mt * 16 + g;
            int col = bn + warpN + nt * 8 + tg * 2;
            *(float2*)&C[(size_t)row * N + col] =
                make_float2(acc[mt][nt][0], acc[mt][nt][1]);
            *(float2*)&C[(size_t)(row + 8) * N + col] =
                make_float2(acc[mt][nt][2], acc[mt][nt][3]);
        }
}

// ---------------------------------------------------------------------------
// RoPE: read fp32 g_Q/g_K, rotate, (Q scaled by 1/8), write bf16 hi/lo splits.
// ---------------------------------------------------------------------------
__global__ void rope_split_kernel(const float* __restrict__ fcos, const float* __restrict__ fsin)
{
    const int NQP = BS * NH * (HD / 2);
    const int NKP = BS * NKV * (HD / 2);
    int idx = blockIdx.x * blockDim.x + threadIdx.x;
    if (idx < NQP) {
        int p = idx & 31;
        int srow = (idx >> 10) & (SS - 1);
        float c = fcos[srow * 32 + p];
        float sn = fsin[srow * 32 + p];
        float2 v = ((const float2*)g_Q)[idx];
        float r0 = (v.x * c - v.y * sn) * 0.125f;
        float r1 = (v.x * sn + v.y * c) * 0.125f;
        __nv_bfloat16 h0 = __float2bfloat16(r0), h1 = __float2bfloat16(r1);
        __nv_bfloat16 l0 = __float2bfloat16(r0 - __bfloat162float(h0));
        __nv_bfloat16 l1 = __float2bfloat16(r1 - __bfloat162float(h1));
        ((unsigned*)g_Qh)[idx] = pkbf(h0, h1);
        ((unsigned*)g_Ql)[idx] = pkbf(l0, l1);
    } else if (idx < NQP + NKP) {
        int j = idx - NQP;
        int p = j & 31;
        int srow = (j >> 8) & (SS - 1);
        float c = fcos[srow * 32 + p];
        float sn = fsin[srow * 32 + p];
        float2 v = ((const float2*)g_K)[j];
        float r0 = v.x * c - v.y * sn;
        float r1 = v.x * sn + v.y * c;
        __nv_bfloat16 h0 = __float2bfloat16(r0), h1 = __float2bfloat16(r1);
        __nv_bfloat16 l0 = __float2bfloat16(r0 - __bfloat162float(h0));
        __nv_bfloat16 l1 = __float2bfloat16(r1 - __bfloat162float(h1));
        ((unsigned*)g_Kh)[j] = pkbf(h0, h1);
        ((unsigned*)g_Kl)[j] = pkbf(l0, l1);
    }
}

// ---------------------------------------------------------------------------
// Causal flash attention, bf16-split mma.sync.
// CTA: 128 q-rows x 64 kv; 4 warps, each warp 32 q-rows (2 m16 tiles).
// K/V fragments amortized over 2 mtiles. Smem regions aliased for Q staging.
// ---------------------------------------------------------------------------
#define ASTR 72
#define AROWS (64*ASTR)   /* elems per 64-row buffer: 4608 */

__global__ __launch_bounds__(128) void attn_mma_kernel()
{
    __shared__ __nv_bfloat16 sm[4 * AROWS];   // 36864 bytes

    const int qt = gridDim.x - 1 - blockIdx.x;   // heavy tiles first
    const int h  = blockIdx.y;
    const int b  = blockIdx.z;
    const int hk = h >> 2;
    const int tid  = threadIdx.x;
    const int lane = tid & 31;
    const int wid  = tid >> 5;
    const int g    = lane >> 2;
    const int tg   = lane & 3;
    const int m0   = wid * 32;
    const int q0   = qt * 128;

    // ---- stage Q (128 rows): hi at sm[0..9216), lo at sm[9216..18432) elems
#pragma unroll
    for (int it = 0; it < 8; it++) {
        int lin = tid + it * 128;          // 0..1023
        int r = lin >> 3, d8 = (lin & 7) * 8;
        size_t gb = (size_t)(b * SS + q0 + r) * DD + h * HD + d8;
        *(uint4*)&sm[r * ASTR + d8]             = *(const uint4*)(g_Qh + gb);
        *(uint4*)&sm[2 * AROWS + r * ASTR + d8] = *(const uint4*)(g_Ql + gb);
    }
    __syncthreads();

    unsigned qh[2][4][4], ql[2][4][4];
#pragma unroll
    for (int mt = 0; mt < 2; mt++) {
        int arow = m0 + mt * 16 + (lane & 15);
#pragma unroll
        for (int kk = 0; kk < 4; kk++) {
            int acol = kk * 16 + (lane >> 4) * 8;
            ldmx4(qh[mt][kk], &sm[arow * ASTR + acol]);
            ldmx4(ql[mt][kk], &sm[2 * AROWS + arow * ASTR + acol]);
        }
    }
    __syncthreads();

    __nv_bfloat16* sKH = sm;
    __nv_bfloat16* sKL = sm + AROWS;
    __nv_bfloat16* sVH = sm + 2 * AROWS;
    __nv_bfloat16* sVL = sm + 3 * AROWS;

    float oO[2][8][4];
#pragma unroll
    for (int mt = 0; mt < 2; mt++)
#pragma unroll
        for (int i = 0; i < 8; i++)
#pragma unroll
            for (int c = 0; c < 4; c++) oO[mt][i][c] = 0.f;
    float mrow[2][2] = {{-1e30f, -1e30f}, {-1e30f, -1e30f}};
    float lrow[2][2] = {{0.f, 0.f}, {0.f, 0.f}};

    const int nkt = 2 * qt + 2;
    for (int kt = 0; kt < nkt; kt++) {
        // ---- load K/V tile (64 rows, hi/lo) ----
#pragma unroll
        for (int it = 0; it < 4; it++) {
            int lin = tid + it * 128;      // 0..511
            int r = lin >> 3, d8 = (lin & 7) * 8;
            size_t gb = (size_t)(b * SS + kt * 64 + r) * KVD + hk * HD + d8;
            *(uint4*)&sKH[r * ASTR + d8] = *(const uint4*)(g_Kh + gb);
            *(uint4*)&sKL[r * ASTR + d8] = *(const uint4*)(g_Kl + gb);
            *(uint4*)&sVH[r * ASTR + d8] = *(const uint4*)(g_Vh + gb);
            *(uint4*)&sVL[r * ASTR + d8] = *(const uint4*)(g_Vl + gb);
        }
        __syncthreads();

        // ---- S = Q K^T ----
        float sS[2][8][4];
#pragma unroll
        for (int mt = 0; mt < 2; mt++)
#pragma unroll
            for (int i = 0; i < 8; i++)
#pragma unroll
                for (int c = 0; c < 4; c++) sS[mt][i][c] = 0.f;

        {
            int brow_base = (lane & 7) + ((lane >> 4) & 1) * 8;
            int bcol = ((lane >> 3) & 1) * 8;
#pragma unroll
            for (int kk = 0; kk < 4; kk++) {
#pragma unroll
                for (int ntp = 0; ntp < 4; ntp++) {
                    unsigned kbh[4], kbl[4];
                    ldmx4(kbh, &sKH[(ntp * 16 + brow_base) * ASTR + kk * 16 + bcol]);
                    ldmx4(kbl, &sKL[(ntp * 16 + brow_base) * ASTR + kk * 16 + bcol]);
#pragma unroll
                    for (int mt = 0; mt < 2; mt++) {
                        mma_bf16(sS[mt][2 * ntp],     qh[mt][kk], kbh);
                        mma_bf16(sS[mt][2 * ntp],     qh[mt][kk], kbl);
                        mma_bf16(sS[mt][2 * ntp],     ql[mt][kk], kbh);
                        mma_bf16(sS[mt][2 * ntp + 1], qh[mt][kk], kbh + 2);
                        mma_bf16(sS[mt][2 * ntp + 1], qh[mt][kk], kbl + 2);
                        mma_bf16(sS[mt][2 * ntp + 1], ql[mt][kk], kbh + 2);
                    }
                }
            }
        }

        // ---- causal mask (global coords; only diagonal-region kt) ----
        if (kt >= 2 * qt) {
#pragma unroll
            for (int mt = 0; mt < 2; mt++)
#pragma unroll
                for (int nt = 0; nt < 8; nt++)
#pragma unroll
                    for (int c = 0; c < 4; c++) {
                        int colg = kt * 64 + nt * 8 + 2 * tg + (c & 1);
                        int rowg = q0 + m0 + mt * 16 + g + ((c >> 1) & 1) * 8;
                        if (colg > rowg) sS[mt][nt][c] = -1e30f;
                    }
        }

        // ---- online softmax ----
        float corr[2][2];
#pragma unroll
        for (int mt = 0; mt < 2; mt++)
#pragma unroll
            for (int rr = 0; rr < 2; rr++) {
                float mx = -1e30f;
#pragma unroll
                for (int nt = 0; nt < 8; nt++)
                    mx = fmaxf(mx, fmaxf(sS[mt][nt][2 * rr], sS[mt][nt][2 * rr + 1]));
                mx = fmaxf(mx, __shfl_xor_sync(0xffffffffu, mx, 1));
                mx = fmaxf(mx, __shfl_xor_sync(0xffffffffu, mx, 2));
                float mn = fmaxf(mrow[mt][rr], mx);
                corr[mt][rr] = __expf(mrow[mt][rr] - mn);
                float lt = 0.f;
#pragma unroll
                for (int nt = 0; nt < 8; nt++) {
                    float e0 = __expf(sS[mt][nt][2 * rr]     - mn);
                    float e1 = __expf(sS[mt][nt][2 * rr + 1] - mn);
                    sS[mt][nt][2 * rr] = e0; sS[mt][nt][2 * rr + 1] = e1;
                    lt += e0 + e1;
                }
                lt += __shfl_xor_sync(0xffffffffu, lt, 1);
                lt += __shfl_xor_sync(0xffffffffu, lt, 2);
                lrow[mt][rr] = lrow[mt][rr] * corr[mt][rr] + lt;
                mrow[mt][rr] = mn;
            }
#pragma unroll
        for (int mt = 0; mt < 2; mt++)
#pragma unroll
            for (int nt = 0; nt < 8; nt++) {
                oO[mt][nt][0] *= corr[mt][0]; oO[mt][nt][1] *= corr[mt][0];
                oO[mt][nt][2] *= corr[mt][1]; oO[mt][nt][3] *= corr[mt][1];
            }

        // ---- O += P V ----
        {
            int vrow_base = (lane & 15);
            int vcol = (lane >> 4) * 8;
#pragma unroll
            for (int kk2 = 0; kk2 < 4; kk2++) {
                unsigned aPh[2][4], aPl[2][4];
#pragma unroll
                for (int mt = 0; mt < 2; mt++)
#pragma unroll
                    for (int half = 0; half < 2; half++) {
                        int nt = 2 * kk2 + half;
                        __nv_bfloat16 h0 = __float2bfloat16(sS[mt][nt][0]);
                        __nv_bfloat16 h1 = __float2bfloat16(sS[mt][nt][1]);
                        __nv_bfloat16 h2 = __float2bfloat16(sS[mt][nt][2]);
                        __nv_bfloat16 h3 = __float2bfloat16(sS[mt][nt][3]);
                        aPh[mt][2 * half]     = pkbf(h0, h1);
                        aPh[mt][2 * half + 1] = pkbf(h2, h3);
                        __nv_bfloat16 l0 = __float2bfloat16(sS[mt][nt][0] - __bfloat162float(h0));
                        __nv_bfloat16 l1 = __float2bfloat16(sS[mt][nt][1] - __bfloat162float(h1));
                        __nv_bfloat16 l2 = __float2bfloat16(sS[mt][nt][2] - __bfloat162float(h2));
                        __nv_bfloat16 l3 = __float2bfloat16(sS[mt][nt][3] - __bfloat162float(h3));
                        aPl[mt][2 * half]     = pkbf(l0, l1);
                        aPl[mt][2 * half + 1] = pkbf(l2, l3);
                    }
#pragma unroll
                for (int dtp = 0; dtp < 4; dtp++) {
                    unsigned vbh[4], vbl[4];
                    ldmx4t(vbh, &sVH[(kk2 * 16 + vrow_base) * ASTR + dtp * 16 + vcol]);
                    ldmx4t(vbl, &sVL[(kk2 * 16 + vrow_base) * ASTR + dtp * 16 + vcol]);
#pragma unroll
                    for (int mt = 0; mt < 2; mt++) {
                        mma_bf16(oO[mt][2 * dtp],     aPh[mt], vbh);
                        mma_bf16(oO[mt][2 * dtp],     aPh[mt], vbl);
                        mma_bf16(oO[mt][2 * dtp],     aPl[mt], vbh);
                        mma_bf16(oO[mt][2 * dtp + 1], aPh[mt], vbh + 2);
                        mma_bf16(oO[mt][2 * dtp + 1], aPh[mt], vbl + 2);
                        mma_bf16(oO[mt][2 * dtp + 1], aPl[mt], vbh + 2);
                    }
                }
            }
        }
        __syncthreads();
    }

    // ---- epilogue ----
#pragma unroll
    for (int mt = 0; mt < 2; mt++) {
        float inv0 = 1.0f / lrow[mt][0];
        float inv1 = 1.0f / lrow[mt][1];
#pragma unroll
        for (int nt = 0; nt < 8; nt++) {
            int col = h * HD + nt * 8 + 2 * tg;
            size_t off0 = (size_t)(b * SS + q0 + m0 + mt * 16 + g) * DD + col;
            size_t off1 = off0 + (size_t)8 * DD;
            float f0 = oO[mt][nt][0] * inv0, f1 = oO[mt][nt][1] * inv0;
            float f2 = oO[mt][nt][2] * inv1, f3 = oO[mt][nt][3] * inv1;
            __nv_bfloat16 h0 = __float2bfloat16(f0), h1 = __float2bfloat16(f1);
            __nv_bfloat16 h2 = __float2bfloat16(f2), h3 = __float2bfloat16(f3);
            *(unsigned*)(g_Ah + off0) = pkbf(h0, h1);
            *(unsigned*)(g_Ah + off1) = pkbf(h2, h3);
            __nv_bfloat16 l0 = __float2bfloat16(f0 - __bfloat162float(h0));
            __nv_bfloat16 l1 = __float2bfloat16(f1 - __bfloat162float(h1));
            __nv_bfloat16 l2 = __float2bfloat16(f2 - __bfloat162float(h2));
            __nv_bfloat16 l3 = __float2bfloat16(f3 - __bfloat162float(h3));
            *(unsigned*)(g_Al + off0) = pkbf(l0, l1);
            *(unsigned*)(g_Al + off1) = pkbf(l2, l3);
        }
    }
}

// ---------------------------------------------------------------------------
extern "C" void kernel_launch(void* const* d_in, const int* in_sizes, int n_in,
                              void* d_out, int out_size)
{
    const float* x   = (const float*)d_in[0];
    const float* fco = (const float*)d_in[1];
    const float* fsi = (const float*)d_in[2];
    const float* wq  = (const float*)d_in[3];
    const float* wk  = (const float*)d_in[4];
    const float* wv  = (const float*)d_in[5];
    const float* wo  = (const float*)d_in[6];
    float* out = (float*)d_out;

    cudaFuncSetAttribute(gemm_mma, cudaFuncAttributeMaxDynamicSharedMemorySize, GEMM_SMEM);

    // split x; transpose+split weights
    cvt_kernel<<<(BS * DD + 255) / 256, 256>>>(x, 0, BS * DD);
    wtr_kernel<<<dim3(DD / 32, DD / 32), dim3(32, 8)>>>(wq, 0, DD, DD);
    wtr_kernel<<<dim3(KVD / 32, DD / 32), dim3(32, 8)>>>(wk, 1, DD, KVD);
    wtr_kernel<<<dim3(KVD / 32, DD / 32), dim3(32, 8)>>>(wv, 2, DD, KVD);
    wtr_kernel<<<dim3(DD / 32, DD / 32), dim3(32, 8)>>>(wo, 3, DD, DD);

    // projections
    gemm_mma<<<dim3(DD / 128, BS / 128), 128, GEMM_SMEM>>>(0, 0, nullptr, 0, BS, DD, DD);
    gemm_mma<<<dim3(KVD / 128, BS / 128), 128, GEMM_SMEM>>>(0, 1, nullptr, 1, BS, KVD, DD);
    gemm_mma<<<dim3(KVD / 128, BS / 128), 128, GEMM_SMEM>>>(0, 2, nullptr, 2, BS, KVD, DD);

    // RoPE -> bf16 splits (Q scaled by 1/8); V -> bf16 splits
    {
        int total = BS * NH * (HD / 2) + BS * NKV * (HD / 2);
        rope_split_kernel<<<(total + 255) / 256, 256>>>(fco, fsi);
    }
    cvt_kernel<<<(BS * KVD + 255) / 256, 256>>>(nullptr, 1, BS * KVD);

    // attention (128 q-rows per CTA)
    attn_mma_kernel<<<dim3(SS / 128, NH, BB), 128>>>();

    // output projection
    gemm_mma<<<dim3(DD / 128, BS / 128), 128, GEMM_SMEM>>>(1, 3, out, -1, BS, DD, DD);
}

// round 9
// speedup vs baseline: 1.0666x; 1.0666x over previous
#include <cuda_runtime.h>
#include <cuda_bf16.h>
#include <math.h>
#include <stdint.h>

#define BB 2
#define SS 2048
#define DD 2048
#define NH 32
#define NKV 8
#define HD 64
#define KVD (NKV*HD)   /* 512 */
#define BS (BB*SS)     /* 4096 */
#define NQKV (DD + 2*KVD)  /* 3072 */

// bf16 hi/lo split scratch
__device__ __nv_bfloat16 g_xh[BS*DD],  g_xl[BS*DD];
__device__ __nv_bfloat16 g_Ah[BS*DD],  g_Al[BS*DD];
__device__ __nv_bfloat16 g_Qh[BS*DD],  g_Ql[BS*DD];
__device__ __nv_bfloat16 g_Kh[BS*KVD], g_Kl[BS*KVD];
__device__ __nv_bfloat16 g_Vh[BS*KVD], g_Vl[BS*KVD];
// transposed weight splits: merged [3072 x 2048] for QKV, [2048 x 2048] for O
__device__ __nv_bfloat16 g_wTh[NQKV*DD], g_wTl[NQKV*DD];
__device__ __nv_bfloat16 g_woTh[DD*DD],  g_woTl[DD*DD];

// ---------------------------------------------------------------------------
// helpers
// ---------------------------------------------------------------------------
__device__ __forceinline__ uint32_t smem_u32(const void* p) {
    uint32_t a;
    asm("{ .reg .u64 t; cvta.to.shared.u64 t, %1; cvt.u32.u64 %0, t; }"
        : "=r"(a) : "l"(p));
    return a;
}

__device__ __forceinline__ unsigned pkbf(__nv_bfloat16 a, __nv_bfloat16 b)
{
    return (unsigned)__bfloat16_as_ushort(a) | ((unsigned)__bfloat16_as_ushort(b) << 16);
}

__device__ __forceinline__ void mma_bf16(float* c, const unsigned* a, const unsigned* b)
{
    asm volatile(
        "mma.sync.aligned.m16n8k16.row.col.f32.bf16.bf16.f32 "
        "{%0,%1,%2,%3}, {%4,%5,%6,%7}, {%8,%9}, {%0,%1,%2,%3};\n"
        : "+f"(c[0]), "+f"(c[1]), "+f"(c[2]), "+f"(c[3])
        : "r"(a[0]), "r"(a[1]), "r"(a[2]), "r"(a[3]), "r"(b[0]), "r"(b[1]));
}

__device__ __forceinline__ void ldmx4(unsigned* r, const __nv_bfloat16* p)
{
    unsigned a = smem_u32(p);
    asm volatile("ldmatrix.sync.aligned.m8n8.x4.shared.b16 {%0,%1,%2,%3}, [%4];"
                 : "=r"(r[0]), "=r"(r[1]), "=r"(r[2]), "=r"(r[3]) : "r"(a));
}
__device__ __forceinline__ void ldmx4t(unsigned* r, const __nv_bfloat16* p)
{
    unsigned a = smem_u32(p);
    asm volatile("ldmatrix.sync.aligned.m8n8.x4.trans.shared.b16 {%0,%1,%2,%3}, [%4];"
                 : "=r"(r[0]), "=r"(r[1]), "=r"(r[2]), "=r"(r[3]) : "r"(a));
}

// split fp32 -> bf16 hi/lo pair packed stores
__device__ __forceinline__ void split_store(__nv_bfloat16* bh, __nv_bfloat16* bl,
                                            size_t off, float f0, float f1)
{
    __nv_bfloat16 h0 = __float2bfloat16(f0), h1 = __float2bfloat16(f1);
    *(unsigned*)(bh + off) = pkbf(h0, h1);
    __nv_bfloat16 l0 = __float2bfloat16(f0 - __bfloat162float(h0));
    __nv_bfloat16 l1 = __float2bfloat16(f1 - __bfloat162float(h1));
    *(unsigned*)(bl + off) = pkbf(l0, l1);
}

// ---------------------------------------------------------------------------
// fp32 x -> (hi, lo) bf16 split
// ---------------------------------------------------------------------------
__global__ void cvt_kernel(const float* __restrict__ src, int n)
{
    int i = blockIdx.x * blockDim.x + threadIdx.x;
    if (i >= n) return;
    float v = src[i];
    __nv_bfloat16 hi = __float2bfloat16(v);
    g_xh[i] = hi;
    g_xl[i] = __float2bfloat16(v - __bfloat162float(hi));
}

// ---------------------------------------------------------------------------
// Weight transpose + split: w [K,N] fp32 -> wT hi/lo rows [nofs .. nofs+N)
// wsel: 0 = merged QKV buffer, 1 = wo buffer.
// ---------------------------------------------------------------------------
__global__ void wtr_kernel(const float* __restrict__ w, int nofs, int wsel, int N)
{
    __shared__ float t[32][33];
    __nv_bfloat16* ph = wsel ? g_woTh : g_wTh;
    __nv_bfloat16* pl = wsel ? g_woTl : g_wTl;
    int n0 = blockIdx.x * 32, k0 = blockIdx.y * 32;
    int tx = threadIdx.x, ty = threadIdx.y;
#pragma unroll
    for (int yy = 0; yy < 4; yy++) {
        int k = k0 + ty + yy * 8;
        t[ty + yy * 8][tx] = w[(size_t)k * N + n0 + tx];
    }
    __syncthreads();
#pragma unroll
    for (int yy = 0; yy < 4; yy++) {
        int n = n0 + ty + yy * 8;
        float v = t[tx][ty + yy * 8];
        __nv_bfloat16 hi = __float2bfloat16(v);
        __nv_bfloat16 lo = __float2bfloat16(v - __bfloat162float(hi));
        ph[(size_t)(nofs + n) * DD + k0 + tx] = hi;
        pl[(size_t)(nofs + n) * DD + k0 + tx] = lo;
    }
}

// ---------------------------------------------------------------------------
// bf16-split GEMM: 128x128 CTA tile, 4 warps, warp tile 64x64, BK=32,
// cp.async double buffer. K fixed = 2048.
// asel: 0 = x splits, 1 = attn-out splits.
// bsel: 0 = merged QKV wT, 1 = woT.
// osel: 0 = fused RoPE+split epilogue into g_Q*/g_K*/g_V* (QKV gemm)
//       1 = plain fp32 store to Cext with row stride DD (O gemm)
// ---------------------------------------------------------------------------
#define GSTR 40
#define GMAT (128*GSTR*2)
#define GSTAGE (4*GMAT)
#define GEMM_SMEM (2*GSTAGE)

__global__ __launch_bounds__(128) void gemm_mma(int asel, int bsel,
                                                float* Cext, int osel,
                                                const float* __restrict__ fcos,
                                                const float* __restrict__ fsin)
{
    extern __shared__ char dsm[];
    const int K = DD;

    const __nv_bfloat16* Ah = asel ? g_Ah : g_xh;
    const __nv_bfloat16* Al = asel ? g_Al : g_xl;
    const __nv_bfloat16* Bh = bsel ? g_woTh : g_wTh;
    const __nv_bfloat16* Bl = bsel ? g_woTl : g_wTl;

    const int tid  = threadIdx.x;
    const int lane = tid & 31;
    const int wid  = tid >> 5;
    const int g    = lane >> 2;
    const int tg   = lane & 3;
    const int warpM = (wid >> 1) * 64;
    const int warpN = (wid & 1) * 64;
    const int bm = blockIdx.y * 128;
    const int bn = blockIdx.x * 128;

    const __nv_bfloat16* srcs[4] = {Ah, Al, Bh, Bl};

    float acc[4][8][4];
#pragma unroll
    for (int a = 0; a < 4; a++)
#pragma unroll
        for (int b = 0; b < 8; b++)
#pragma unroll
            for (int c = 0; c < 4; c++) acc[a][b][c] = 0.f;

    auto docopy = [&](int ch) {
        const uint32_t sb = smem_u32(dsm) + (ch & 1) * GSTAGE;
#pragma unroll
        for (int it = 0; it < 16; it++) {
            int o = tid + it * 128;
            int mat = o >> 9;
            int idx = o & 511;
            int r = idx >> 2, c8 = (idx & 3) * 8;
            int rowbase = (mat < 2) ? bm : bn;
            uint32_t so = sb + mat * GMAT + r * (GSTR * 2) + c8 * 2;
            const __nv_bfloat16* gp = srcs[mat] + (size_t)(rowbase + r) * K + ch * 32 + c8;
            asm volatile("cp.async.cg.shared.global [%0], [%1], 16;\n"
                         :: "r"(so), "l"(gp));
        }
        asm volatile("cp.async.commit_group;\n");
    };

    const int nkb = K / 32;
    docopy(0);

    for (int kb = 0; kb < nkb; kb++) {
        if (kb + 1 < nkb) {
            docopy(kb + 1);
            asm volatile("cp.async.wait_group 1;\n" ::: "memory");
        } else {
            asm volatile("cp.async.wait_group 0;\n" ::: "memory");
        }
        __syncthreads();

        const __nv_bfloat16* sAh = (const __nv_bfloat16*)(dsm + (kb & 1) * GSTAGE);
        const __nv_bfloat16* sAl = sAh + 128 * GSTR;
        const __nv_bfloat16* sBh = sAl + 128 * GSTR;
        const __nv_bfloat16* sBl = sBh + 128 * GSTR;

#pragma unroll
        for (int ks = 0; ks < 2; ks++) {
            const int kc = ks * 16;
            unsigned ah[4][4], al[4][4];
            {
                int arow = warpM + (lane & 15);
                int acol = kc + (lane >> 4) * 8;
#pragma unroll
                for (int mt = 0; mt < 4; mt++) {
                    ldmx4(ah[mt], &sAh[(arow + mt * 16) * GSTR + acol]);
                    ldmx4(al[mt], &sAl[(arow + mt * 16) * GSTR + acol]);
                }
            }
            unsigned bh[4][4], bl[4][4];
            {
                int brow = (lane & 7) + ((lane >> 4) & 1) * 8;
                int bcol = kc + ((lane >> 3) & 1) * 8;
#pragma unroll
                for (int ng = 0; ng < 4; ng++) {
                    ldmx4(bh[ng], &sBh[(warpN + ng * 16 + brow) * GSTR + bcol]);
                    ldmx4(bl[ng], &sBl[(warpN + ng * 16 + brow) * GSTR + bcol]);
                }
            }
#pragma unroll
            for (int mt = 0; mt < 4; mt++)
#pragma unroll
                for (int ng = 0; ng < 4; ng++) {
                    mma_bf16(acc[mt][2 * ng],     ah[mt], bh[ng]);
                    mma_bf16(acc[mt][2 * ng],     ah[mt], bl[ng]);
                    mma_bf16(acc[mt][2 * ng],     al[mt], bh[ng]);
                    mma_bf16(acc[mt][2 * ng + 1], ah[mt], bh[ng] + 2);
                    mma_bf16(acc[mt][2 * ng + 1], ah[mt], bl[ng] + 2);
                    mma_bf16(acc[mt][2 * ng + 1], al[mt], bh[ng] + 2);
                }
        }
        __syncthreads();
    }

    if (osel == 1) {
        // plain fp32 epilogue (O projection -> external out, stride DD)
#pragma unroll
        for (int mt = 0; mt < 4; mt++)
#pragma unroll
            for (int nt = 0; nt < 8; nt++) {
                int row = bm + warpM + mt * 16 + g;
                int col = bn + warpN + nt * 8 + tg * 2;
                *(float2*)&Cext[(size_t)row * DD + col] =
                    make_float2(acc[mt][nt][0], acc[mt][nt][1]);
                *(float2*)&Cext[(size_t)(row + 8) * DD + col] =
                    make_float2(acc[mt][nt][2], acc[mt][nt][3]);
            }
        return;
    }

    // fused RoPE + bf16-split epilogue (QKV gemm). Segment is CTA-uniform.
    const int seg = (bn < DD) ? 0 : (bn < DD + KVD) ? 1 : 2;
#pragma unroll
    for (int mt = 0; mt < 4; mt++) {
        int row0 = bm + warpM + mt * 16 + g;     // and row0+8
#pragma unroll
        for (int nt = 0; nt < 8; nt++) {
            int col = bn + warpN + nt * 8 + tg * 2;   // even
            float a0 = acc[mt][nt][0], a1 = acc[mt][nt][1];   // row0
            float a2 = acc[mt][nt][2], a3 = acc[mt][nt][3];   // row0+8
            if (seg == 2) {
                // V: plain split
                size_t off0 = (size_t)row0 * KVD + (col - DD - KVD);
                split_store(g_Vh, g_Vl, off0, a0, a1);
                split_store(g_Vh, g_Vl, off0 + 8 * KVD, a2, a3);
            } else {
                int p = (col & 63) >> 1;
                int s0 = row0 & (SS - 1);
                int s1 = (row0 + 8) & (SS - 1);
                float c0 = fcos[s0 * 32 + p], sn0 = fsin[s0 * 32 + p];
                float c1 = fcos[s1 * 32 + p], sn1 = fsin[s1 * 32 + p];
                float r0 = a0 * c0 - a1 * sn0;
                float r1 = a0 * sn0 + a1 * c0;
                float r2 = a2 * c1 - a3 * sn1;
                float r3 = a2 * sn1 + a3 * c1;
                if (seg == 0) {
                    // Q: scale by 1/8 (fold 1/sqrt(HD))
                    r0 *= 0.125f; r1 *= 0.125f; r2 *= 0.125f; r3 *= 0.125f;
                    size_t off0 = (size_t)row0 * DD + col;
                    split_store(g_Qh, g_Ql, off0, r0, r1);
                    split_store(g_Qh, g_Ql, off0 + 8 * DD, r2, r3);
                } else {
                    size_t off0 = (size_t)row0 * KVD + (col - DD);
                    split_store(g_Kh, g_Kl, off0, r0, r1);
                    split_store(g_Kh, g_Kl, off0 + 8 * KVD, r2, r3);
                }
            }
        }
    }
}

// ---------------------------------------------------------------------------
// Causal flash attention, bf16-split mma.sync (unchanged from Round 8).
// CTA: 128 q-rows x 64 kv; 4 warps, each warp 32 q-rows (2 m16 tiles).
// ---------------------------------------------------------------------------
#define ASTR 72
#define AROWS (64*ASTR)

__global__ __launch_bounds__(128) void attn_mma_kernel()
{
    __shared__ __nv_bfloat16 sm[4 * AROWS];

    const int qt = gridDim.x - 1 - blockIdx.x;
    const int h  = blockIdx.y;
    const int b  = blockIdx.z;
    const int hk = h >> 2;
    const int tid  = threadIdx.x;
    const int lane = tid & 31;
    const int wid  = tid >> 5;
    const int g    = lane >> 2;
    const int tg   = lane & 3;
    const int m0   = wid * 32;
    const int q0   = qt * 128;

#pragma unroll
    for (int it = 0; it < 8; it++) {
        int lin = tid + it * 128;
        int r = lin >> 3, d8 = (lin & 7) * 8;
        size_t gb = (size_t)(b * SS + q0 + r) * DD + h * HD + d8;
        *(uint4*)&sm[r * ASTR + d8]             = *(const uint4*)(g_Qh + gb);
        *(uint4*)&sm[2 * AROWS + r * ASTR + d8] = *(const uint4*)(g_Ql + gb);
    }
    __syncthreads();

    unsigned qh[2][4][4], ql[2][4][4];
#pragma unroll
    for (int mt = 0; mt < 2; mt++) {
        int arow = m0 + mt * 16 + (lane & 15);
#pragma unroll
        for (int kk = 0; kk < 4; kk++) {
            int acol = kk * 16 + (lane >> 4) * 8;
            ldmx4(qh[mt][kk], &sm[arow * ASTR + acol]);
            ldmx4(ql[mt][kk], &sm[2 * AROWS + arow * ASTR + acol]);
        }
    }
    __syncthreads();

    __nv_bfloat16* sKH = sm;
    __nv_bfloat16* sKL = sm + AROWS;
    __nv_bfloat16* sVH = sm + 2 * AROWS;
    __nv_bfloat16* sVL = sm + 3 * AROWS;

    float oO[2][8][4];
#pragma unroll
    for (int mt = 0; mt < 2; mt++)
#pragma unroll
        for (int i = 0; i < 8; i++)
#pragma unroll
            for (int c = 0; c < 4; c++) oO[mt][i][c] = 0.f;
    float mrow[2][2] = {{-1e30f, -1e30f}, {-1e30f, -1e30f}};
    float lrow[2][2] = {{0.f, 0.f}, {0.f, 0.f}};

    const int nkt = 2 * qt + 2;
    for (int kt = 0; kt < nkt; kt++) {
#pragma unroll
        for (int it = 0; it < 4; it++) {
            int lin = tid + it * 128;
            int r = lin >> 3, d8 = (lin & 7) * 8;
            size_t gb = (size_t)(b * SS + kt * 64 + r) * KVD + hk * HD + d8;
            *(uint4*)&sKH[r * ASTR + d8] = *(const uint4*)(g_Kh + gb);
            *(uint4*)&sKL[r * ASTR + d8] = *(const uint4*)(g_Kl + gb);
            *(uint4*)&sVH[r * ASTR + d8] = *(const uint4*)(g_Vh + gb);
            *(uint4*)&sVL[r * ASTR + d8] = *(const uint4*)(g_Vl + gb);
        }
        __syncthreads();

        float sS[2][8][4];
#pragma unroll
        for (int mt = 0; mt < 2; mt++)
#pragma unroll
            for (int i = 0; i < 8; i++)
#pragma unroll
                for (int c = 0; c < 4; c++) sS[mt][i][c] = 0.f;

        {
            int brow_base = (lane & 7) + ((lane >> 4) & 1) * 8;
            int bcol = ((lane >> 3) & 1) * 8;
#pragma unroll
            for (int kk = 0; kk < 4; kk++) {
#pragma unroll
                for (int ntp = 0; ntp < 4; ntp++) {
                    unsigned kbh[4], kbl[4];
                    ldmx4(kbh, &sKH[(ntp * 16 + brow_base) * ASTR + kk * 16 + bcol]);
                    ldmx4(kbl, &sKL[(ntp * 16 + brow_base) * ASTR + kk * 16 + bcol]);
#pragma unroll
                    for (int mt = 0; mt < 2; mt++) {
                        mma_bf16(sS[mt][2 * ntp],     qh[mt][kk], kbh);
                        mma_bf16(sS[mt][2 * ntp],     qh[mt][kk], kbl);
                        mma_bf16(sS[mt][2 * ntp],     ql[mt][kk], kbh);
                        mma_bf16(sS[mt][2 * ntp + 1], qh[mt][kk], kbh + 2);
                        mma_bf16(sS[mt][2 * ntp + 1], qh[mt][kk], kbl + 2);
                        mma_bf16(sS[mt][2 * ntp + 1], ql[mt][kk], kbh + 2);
                    }
                }
            }
        }

        if (kt >= 2 * qt) {
#pragma unroll
            for (int mt = 0; mt < 2; mt++)
#pragma unroll
                for (int nt = 0; nt < 8; nt++)
#pragma unroll
                    for (int c = 0; c < 4; c++) {
                        int colg = kt * 64 + nt * 8 + 2 * tg + (c & 1);
                        int rowg = q0 + m0 + mt * 16 + g + ((c >> 1) & 1) * 8;
                        if (colg > rowg) sS[mt][nt][c] = -1e30f;
                    }
        }

        float corr[2][2];
#pragma unroll
        for (int mt = 0; mt < 2; mt++)
#pragma unroll
            for (int rr = 0; rr < 2; rr++) {
                float mx = -1e30f;
#pragma unroll
                for (int nt = 0; nt < 8; nt++)
                    mx = fmaxf(mx, fmaxf(sS[mt][nt][2 * rr], sS[mt][nt][2 * rr + 1]));
                mx = fmaxf(mx, __shfl_xor_sync(0xffffffffu, mx, 1));
                mx = fmaxf(mx, __shfl_xor_sync(0xffffffffu, mx, 2));
                float mn = fmaxf(mrow[mt][rr], mx);
                corr[mt][rr] = __expf(mrow[mt][rr] - mn);
                float lt = 0.f;
#pragma unroll
                for (int nt = 0; nt < 8; nt++) {
                    float e0 = __expf(sS[mt][nt][2 * rr]     - mn);
                    float e1 = __expf(sS[mt][nt][2 * rr + 1] - mn);
                    sS[mt][nt][2 * rr] = e0; sS[mt][nt][2 * rr + 1] = e1;
                    lt += e0 + e1;
                }
                lt += __shfl_xor_sync(0xffffffffu, lt, 1);
                lt += __shfl_xor_sync(0xffffffffu, lt, 2);
                lrow[mt][rr] = lrow[mt][rr] * corr[mt][rr] + lt;
                mrow[mt][rr] = mn;
            }
#pragma unroll
        for (int mt = 0; mt < 2; mt++)
#pragma unroll
            for (int nt = 0; nt < 8; nt++) {
                oO[mt][nt][0] *= corr[mt][0]; oO[mt][nt][1] *= corr[mt][0];
                oO[mt][nt][2] *= corr[mt][1]; oO[mt][nt][3] *= corr[mt][1];
            }

        {
            int vrow_base = (lane & 15);
            int vcol = (lane >> 4) * 8;
#pragma unroll
            for (int kk2 = 0; kk2 < 4; kk2++) {
                unsigned aPh[2][4], aPl[2][4];
#pragma unroll
                for (int mt = 0; mt < 2; mt++)
#pragma unroll
                    for (int half = 0; half < 2; half++) {
                        int nt = 2 * kk2 + half;
                        __nv_bfloat16 h0 = __float2bfloat16(sS[mt][nt][0]);
                        __nv_bfloat16 h1 = __float2bfloat16(sS[mt][nt][1]);
                        __nv_bfloat16 h2 = __float2bfloat16(sS[mt][nt][2]);
                        __nv_bfloat16 h3 = __float2bfloat16(sS[mt][nt][3]);
                        aPh[mt][2 * half]     = pkbf(h0, h1);
                        aPh[mt][2 * half + 1] = pkbf(h2, h3);
                        __nv_bfloat16 l0 = __float2bfloat16(sS[mt][nt][0] - __bfloat162float(h0));
                        __nv_bfloat16 l1 = __float2bfloat16(sS[mt][nt][1] - __bfloat162float(h1));
                        __nv_bfloat16 l2 = __float2bfloat16(sS[mt][nt][2] - __bfloat162float(h2));
                        __nv_bfloat16 l3 = __float2bfloat16(sS[mt][nt][3] - __bfloat162float(h3));
                        aPl[mt][2 * half]     = pkbf(l0, l1);
                        aPl[mt][2 * half + 1] = pkbf(l2, l3);
                    }
#pragma unroll
                for (int dtp = 0; dtp < 4; dtp++) {
                    unsigned vbh[4], vbl[4];
                    ldmx4t(vbh, &sVH[(kk2 * 16 + vrow_base) * ASTR + dtp * 16 + vcol]);
                    ldmx4t(vbl, &sVL[(kk2 * 16 + vrow_base) * ASTR + dtp * 16 + vcol]);
#pragma unroll
                    for (int mt = 0; mt < 2; mt++) {
                        mma_bf16(oO[mt][2 * dtp],     aPh[mt], vbh);
                        mma_bf16(oO[mt][2 * dtp],     aPh[mt], vbl);
                        mma_bf16(oO[mt][2 * dtp],     aPl[mt], vbh);
                        mma_bf16(oO[mt][2 * dtp + 1], aPh[mt], vbh + 2);
                        mma_bf16(oO[mt][2 * dtp + 1], aPh[mt], vbl + 2);
                        mma_bf16(oO[mt][2 * dtp + 1], aPl[mt], vbh + 2);
                    }
                }
            }
        }
        __syncthreads();
    }

#pragma unroll
    for (int mt = 0; mt < 2; mt++) {
        float inv0 = 1.0f / lrow[mt][0];
        float inv1 = 1.0f / lrow[mt][1];
#pragma unroll
        for (int nt = 0; nt < 8; nt++) {
            int col = h * HD + nt * 8 + 2 * tg;
            size_t off0 = (size_t)(b * SS + q0 + m0 + mt * 16 + g) * DD + col;
            size_t off1 = off0 + (size_t)8 * DD;
            split_store(g_Ah, g_Al, off0, oO[mt][nt][0] * inv0, oO[mt][nt][1] * inv0);
            split_store(g_Ah, g_Al, off1, oO[mt][nt][2] * inv1, oO[mt][nt][3] * inv1);
        }
    }
}

// ---------------------------------------------------------------------------
extern "C" void kernel_launch(void* const* d_in, const int* in_sizes, int n_in,
                              void* d_out, int out_size)
{
    const float* x   = (const float*)d_in[0];
    const float* fco = (const float*)d_in[1];
    const float* fsi = (const float*)d_in[2];
    const float* wq  = (const float*)d_in[3];
    const float* wk  = (const float*)d_in[4];
    const float* wv  = (const float*)d_in[5];
    const float* wo  = (const float*)d_in[6];
    float* out = (float*)d_out;

    cudaFuncSetAttribute(gemm_mma, cudaFuncAttributeMaxDynamicSharedMemorySize, GEMM_SMEM);

    // split x; transpose+split weights (merged QKV + wo)
    cvt_kernel<<<(BS * DD + 255) / 256, 256>>>(x, BS * DD);
    wtr_kernel<<<dim3(DD / 32, DD / 32), dim3(32, 8)>>>(wq, 0, 0, DD);
    wtr_kernel<<<dim3(KVD / 32, DD / 32), dim3(32, 8)>>>(wk, DD, 0, KVD);
    wtr_kernel<<<dim3(KVD / 32, DD / 32), dim3(32, 8)>>>(wv, DD + KVD, 0, KVD);
    wtr_kernel<<<dim3(DD / 32, DD / 32), dim3(32, 8)>>>(wo, 0, 1, DD);

    // merged QKV projection with fused RoPE + bf16-split epilogue
    gemm_mma<<<dim3(NQKV / 128, BS / 128), 128, GEMM_SMEM>>>(0, 0, nullptr, 0, fco, fsi);

    // attention (128 q-rows per CTA)
    attn_mma_kernel<<<dim3(SS / 128, NH, BB), 128>>>();

    // output projection (plain fp32 epilogue -> out)
    gemm_mma<<<dim3(DD / 128, BS / 128), 128, GEMM_SMEM>>>(1, 1, out, 1, fco, fsi);
}

// round 11
// speedup vs baseline: 1.1327x; 1.0619x over previous
#include <cuda_runtime.h>
#include <cuda_fp16.h>
#include <math.h>
#include <stdint.h>

#define BB 2
#define SS 2048
#define DD 2048
#define NH 32
#define NKV 8
#define HD 64
#define KVD (NKV*HD)   /* 512 */
#define BS (BB*SS)     /* 4096 */
#define NQKV (DD + 2*KVD)  /* 3072 */

// fp16 hi/lo split scratch
__device__ __half g_xh[BS*DD],  g_xl[BS*DD];
__device__ __half g_Ah[BS*DD],  g_Al[BS*DD];
__device__ __half g_Qh[BS*DD],  g_Ql[BS*DD];
__device__ __half g_Kh[BS*KVD], g_Kl[BS*KVD];
__device__ __half g_Vh[BS*KVD], g_Vl[BS*KVD];
// transposed weight splits: merged [3072 x 2048] for QKV, [2048 x 2048] for O
__device__ __half g_wTh[NQKV*DD], g_wTl[NQKV*DD];
__device__ __half g_woTh[DD*DD],  g_woTl[DD*DD];

// ---------------------------------------------------------------------------
// helpers
// ---------------------------------------------------------------------------
__device__ __forceinline__ uint32_t smem_u32(const void* p) {
    uint32_t a;
    asm("{ .reg .u64 t; cvta.to.shared.u64 t, %1; cvt.u32.u64 %0, t; }"
        : "=r"(a) : "l"(p));
    return a;
}

__device__ __forceinline__ unsigned pkh(__half a, __half b)
{
    return (unsigned)__half_as_ushort(a) | ((unsigned)__half_as_ushort(b) << 16);
}

__device__ __forceinline__ void mma_f16(float* c, const unsigned* a, const unsigned* b)
{
    asm volatile(
        "mma.sync.aligned.m16n8k16.row.col.f32.f16.f16.f32 "
        "{%0,%1,%2,%3}, {%4,%5,%6,%7}, {%8,%9}, {%0,%1,%2,%3};\n"
        : "+f"(c[0]), "+f"(c[1]), "+f"(c[2]), "+f"(c[3])
        : "r"(a[0]), "r"(a[1]), "r"(a[2]), "r"(a[3]), "r"(b[0]), "r"(b[1]));
}

__device__ __forceinline__ void ldmx4(unsigned* r, const __half* p)
{
    unsigned a = smem_u32(p);
    asm volatile("ldmatrix.sync.aligned.m8n8.x4.shared.b16 {%0,%1,%2,%3}, [%4];"
                 : "=r"(r[0]), "=r"(r[1]), "=r"(r[2]), "=r"(r[3]) : "r"(a));
}
__device__ __forceinline__ void ldmx4t(unsigned* r, const __half* p)
{
    unsigned a = smem_u32(p);
    asm volatile("ldmatrix.sync.aligned.m8n8.x4.trans.shared.b16 {%0,%1,%2,%3}, [%4];"
                 : "=r"(r[0]), "=r"(r[1]), "=r"(r[2]), "=r"(r[3]) : "r"(a));
}

// split fp32 -> fp16 hi/lo pair packed stores
__device__ __forceinline__ void split_store(__half* bh, __half* bl,
                                            size_t off, float f0, float f1)
{
    __half h0 = __float2half(f0), h1 = __float2half(f1);
    *(unsigned*)(bh + off) = pkh(h0, h1);
    __half l0 = __float2half(f0 - __half2float(h0));
    __half l1 = __float2half(f1 - __half2float(h1));
    *(unsigned*)(bl + off) = pkh(l0, l1);
}

// ---------------------------------------------------------------------------
// fp32 x -> (hi, lo) fp16 split
// ---------------------------------------------------------------------------
__global__ void cvt_kernel(const float* __restrict__ src, int n)
{
    int i = blockIdx.x * blockDim.x + threadIdx.x;
    if (i >= n) return;
    float v = src[i];
    __half hi = __float2half(v);
    g_xh[i] = hi;
    g_xl[i] = __float2half(v - __half2float(hi));
}

// ---------------------------------------------------------------------------
// Weight transpose + split: w [K,N] fp32 -> wT hi/lo rows [nofs .. nofs+N)
// ---------------------------------------------------------------------------
__global__ void wtr_kernel(const float* __restrict__ w, int nofs, int wsel, int N)
{
    __shared__ float t[32][33];
    __half* ph = wsel ? g_woTh : g_wTh;
    __half* pl = wsel ? g_woTl : g_wTl;
    int n0 = blockIdx.x * 32, k0 = blockIdx.y * 32;
    int tx = threadIdx.x, ty = threadIdx.y;
#pragma unroll
    for (int yy = 0; yy < 4; yy++) {
        int k = k0 + ty + yy * 8;
        t[ty + yy * 8][tx] = w[(size_t)k * N + n0 + tx];
    }
    __syncthreads();
#pragma unroll
    for (int yy = 0; yy < 4; yy++) {
        int n = n0 + ty + yy * 8;
        float v = t[tx][ty + yy * 8];
        __half hi = __float2half(v);
        __half lo = __float2half(v - __half2float(hi));
        ph[(size_t)(nofs + n) * DD + k0 + tx] = hi;
        pl[(size_t)(nofs + n) * DD + k0 + tx] = lo;
    }
}

// ---------------------------------------------------------------------------
// fp16-split GEMM: 128x128 CTA tile, 4 warps, warp tile 64x64, BK=32,
// cp.async double buffer. K = 2048.
// Product count: 3 for Q/K segments (precision-critical), 2 for V segment
// and the O projection (linear error paths).
// ---------------------------------------------------------------------------
#define GSTR 40
#define GMAT (128*GSTR*2)
#define GSTAGE (4*GMAT)
#define GEMM_SMEM (2*GSTAGE)

__global__ __launch_bounds__(128) void gemm_mma(int asel, int bsel,
                                                float* Cext, int osel,
                                                const float* __restrict__ fcos,
                                                const float* __restrict__ fsin)
{
    extern __shared__ char dsm[];
    const int K = DD;

    const __half* Ah = asel ? g_Ah : g_xh;
    const __half* Al = asel ? g_Al : g_xl;
    const __half* Bh = bsel ? g_woTh : g_wTh;
    const __half* Bl = bsel ? g_woTl : g_wTl;

    const int tid  = threadIdx.x;
    const int lane = tid & 31;
    const int wid  = tid >> 5;
    const int g    = lane >> 2;
    const int tg   = lane & 3;
    const int warpM = (wid >> 1) * 64;
    const int warpN = (wid & 1) * 64;
    const int bm = blockIdx.y * 128;
    const int bn = blockIdx.x * 128;

    // third (Al*Bh) product only for Q/K segments of the QKV gemm
    const bool third = (osel == 0) && (bn < DD + KVD);

    const __half* srcs[4] = {Ah, Al, Bh, Bl};

    float acc[4][8][4];
#pragma unroll
    for (int a = 0; a < 4; a++)
#pragma unroll
        for (int b = 0; b < 8; b++)
#pragma unroll
            for (int c = 0; c < 4; c++) acc[a][b][c] = 0.f;

    auto docopy = [&](int ch) {
        const uint32_t sb = smem_u32(dsm) + (ch & 1) * GSTAGE;
#pragma unroll
        for (int it = 0; it < 16; it++) {
            int o = tid + it * 128;
            int mat = o >> 9;
            int idx = o & 511;
            int r = idx >> 2, c8 = (idx & 3) * 8;
            int rowbase = (mat < 2) ? bm : bn;
            uint32_t so = sb + mat * GMAT + r * (GSTR * 2) + c8 * 2;
            const __half* gp = srcs[mat] + (size_t)(rowbase + r) * K + ch * 32 + c8;
            asm volatile("cp.async.cg.shared.global [%0], [%1], 16;\n"
                         :: "r"(so), "l"(gp));
        }
        asm volatile("cp.async.commit_group;\n");
    };

    const int nkb = K / 32;
    docopy(0);

    for (int kb = 0; kb < nkb; kb++) {
        if (kb + 1 < nkb) {
            docopy(kb + 1);
            asm volatile("cp.async.wait_group 1;\n" ::: "memory");
        } else {
            asm volatile("cp.async.wait_group 0;\n" ::: "memory");
        }
        __syncthreads();

        const __half* sAh = (const __half*)(dsm + (kb & 1) * GSTAGE);
        const __half* sAl = sAh + 128 * GSTR;
        const __half* sBh = sAl + 128 * GSTR;
        const __half* sBl = sBh + 128 * GSTR;

#pragma unroll
        for (int ks = 0; ks < 2; ks++) {
            const int kc = ks * 16;
            unsigned ah[4][4], al[4][4];
            {
                int arow = warpM + (lane & 15);
                int acol = kc + (lane >> 4) * 8;
#pragma unroll
                for (int mt = 0; mt < 4; mt++) {
                    ldmx4(ah[mt], &sAh[(arow + mt * 16) * GSTR + acol]);
                    if (third) ldmx4(al[mt], &sAl[(arow + mt * 16) * GSTR + acol]);
                }
            }
            unsigned bh[4][4], bl[4][4];
            {
                int brow = (lane & 7) + ((lane >> 4) & 1) * 8;
                int bcol = kc + ((lane >> 3) & 1) * 8;
#pragma unroll
                for (int ng = 0; ng < 4; ng++) {
                    ldmx4(bh[ng], &sBh[(warpN + ng * 16 + brow) * GSTR + bcol]);
                    ldmx4(bl[ng], &sBl[(warpN + ng * 16 + brow) * GSTR + bcol]);
                }
            }
#pragma unroll
            for (int mt = 0; mt < 4; mt++)
#pragma unroll
                for (int ng = 0; ng < 4; ng++) {
                    mma_f16(acc[mt][2 * ng],     ah[mt], bh[ng]);
                    mma_f16(acc[mt][2 * ng],     ah[mt], bl[ng]);
                    mma_f16(acc[mt][2 * ng + 1], ah[mt], bh[ng] + 2);
                    mma_f16(acc[mt][2 * ng + 1], ah[mt], bl[ng] + 2);
                    if (third) {
                        mma_f16(acc[mt][2 * ng],     al[mt], bh[ng]);
                        mma_f16(acc[mt][2 * ng + 1], al[mt], bh[ng] + 2);
                    }
                }
        }
        __syncthreads();
    }

    if (osel == 1) {
#pragma unroll
        for (int mt = 0; mt < 4; mt++)
#pragma unroll
            for (int nt = 0; nt < 8; nt++) {
                int row = bm + warpM + mt * 16 + g;
                int col = bn + warpN + nt * 8 + tg * 2;
                *(float2*)&Cext[(size_t)row * DD + col] =
                    make_float2(acc[mt][nt][0], acc[mt][nt][1]);
                *(float2*)&Cext[(size_t)(row + 8) * DD + col] =
                    make_float2(acc[mt][nt][2], acc[mt][nt][3]);
            }
        return;
    }

    // fused RoPE + fp16-split epilogue (QKV gemm). Segment is CTA-uniform.
    const int seg = (bn < DD) ? 0 : (bn < DD + KVD) ? 1 : 2;
#pragma unroll
    for (int mt = 0; mt < 4; mt++) {
        int row0 = bm + warpM + mt * 16 + g;
#pragma unroll
        for (int nt = 0; nt < 8; nt++) {
            int col = bn + warpN + nt * 8 + tg * 2;
            float a0 = acc[mt][nt][0], a1 = acc[mt][nt][1];
            float a2 = acc[mt][nt][2], a3 = acc[mt][nt][3];
            if (seg == 2) {
                size_t off0 = (size_t)row0 * KVD + (col - DD - KVD);
                split_store(g_Vh, g_Vl, off0, a0, a1);
                split_store(g_Vh, g_Vl, off0 + 8 * KVD, a2, a3);
            } else {
                int p = (col & 63) >> 1;
                int s0 = row0 & (SS - 1);
                int s1 = (row0 + 8) & (SS - 1);
                float c0 = fcos[s0 * 32 + p], sn0 = fsin[s0 * 32 + p];
                float c1 = fcos[s1 * 32 + p], sn1 = fsin[s1 * 32 + p];
                float r0 = a0 * c0 - a1 * sn0;
                float r1 = a0 * sn0 + a1 * c0;
                float r2 = a2 * c1 - a3 * sn1;
                float r3 = a2 * sn1 + a3 * c1;
                if (seg == 0) {
                    r0 *= 0.125f; r1 *= 0.125f; r2 *= 0.125f; r3 *= 0.125f;
                    size_t off0 = (size_t)row0 * DD + col;
                    split_store(g_Qh, g_Ql, off0, r0, r1);
                    split_store(g_Qh, g_Ql, off0 + 8 * DD, r2, r3);
                } else {
                    size_t off0 = (size_t)row0 * KVD + (col - DD);
                    split_store(g_Kh, g_Kl, off0, r0, r1);
                    split_store(g_Kh, g_Kl, off0 + 8 * KVD, r2, r3);
                }
            }
        }
    }
}

// ---------------------------------------------------------------------------
// Causal flash attention, fp16-split mma.sync.
// S = QK^T: 3 products (precision-critical). O += P V: 2 products.
// CTA: 128 q-rows x 64 kv; 4 warps x 32 q-rows.
// ---------------------------------------------------------------------------
#define ASTR 72
#define AROWS (64*ASTR)

__global__ __launch_bounds__(128) void attn_mma_kernel()
{
    __shared__ __half sm[4 * AROWS];

    const int qt = gridDim.x - 1 - blockIdx.x;
    const int h  = blockIdx.y;
    const int b  = blockIdx.z;
    const int hk = h >> 2;
    const int tid  = threadIdx.x;
    const int lane = tid & 31;
    const int wid  = tid >> 5;
    const int g    = lane >> 2;
    const int tg   = lane & 3;
    const int m0   = wid * 32;
    const int q0   = qt * 128;

#pragma unroll
    for (int it = 0; it < 8; it++) {
        int lin = tid + it * 128;
        int r = lin >> 3, d8 = (lin & 7) * 8;
        size_t gb = (size_t)(b * SS + q0 + r) * DD + h * HD + d8;
        *(uint4*)&sm[r * ASTR + d8]             = *(const uint4*)(g_Qh + gb);
        *(uint4*)&sm[2 * AROWS + r * ASTR + d8] = *(const uint4*)(g_Ql + gb);
    }
    __syncthreads();

    unsigned qh[2][4][4], ql[2][4][4];
#pragma unroll
    for (int mt = 0; mt < 2; mt++) {
        int arow = m0 + mt * 16 + (lane & 15);
#pragma unroll
        for (int kk = 0; kk < 4; kk++) {
            int acol = kk * 16 + (lane >> 4) * 8;
            ldmx4(qh[mt][kk], &sm[arow * ASTR + acol]);
            ldmx4(ql[mt][kk], &sm[2 * AROWS + arow * ASTR + acol]);
        }
    }
    __syncthreads();

    __half* sKH = sm;
    __half* sKL = sm + AROWS;
    __half* sVH = sm + 2 * AROWS;
    __half* sVL = sm + 3 * AROWS;

    float oO[2][8][4];
#pragma unroll
    for (int mt = 0; mt < 2; mt++)
#pragma unroll
        for (int i = 0; i < 8; i++)
#pragma unroll
            for (int c = 0; c < 4; c++) oO[mt][i][c] = 0.f;
    float mrow[2][2] = {{-1e30f, -1e30f}, {-1e30f, -1e30f}};
    float lrow[2][2] = {{0.f, 0.f}, {0.f, 0.f}};

    const int nkt = 2 * qt + 2;
    for (int kt = 0; kt < nkt; kt++) {
#pragma unroll
        for (int it = 0; it < 4; it++) {
            int lin = tid + it * 128;
            int r = lin >> 3, d8 = (lin & 7) * 8;
            size_t gb = (size_t)(b * SS + kt * 64 + r) * KVD + hk * HD + d8;
            *(uint4*)&sKH[r * ASTR + d8] = *(const uint4*)(g_Kh + gb);
            *(uint4*)&sKL[r * ASTR + d8] = *(const uint4*)(g_Kl + gb);
            *(uint4*)&sVH[r * ASTR + d8] = *(const uint4*)(g_Vh + gb);
            *(uint4*)&sVL[r * ASTR + d8] = *(const uint4*)(g_Vl + gb);
        }
        __syncthreads();

        float sS[2][8][4];
#pragma unroll
        for (int mt = 0; mt < 2; mt++)
#pragma unroll
            for (int i = 0; i < 8; i++)
#pragma unroll
                for (int c = 0; c < 4; c++) sS[mt][i][c] = 0.f;

        {
            int brow_base = (lane & 7) + ((lane >> 4) & 1) * 8;
            int bcol = ((lane >> 3) & 1) * 8;
#pragma unroll
            for (int kk = 0; kk < 4; kk++) {
#pragma unroll
                for (int ntp = 0; ntp < 4; ntp++) {
                    unsigned kbh[4], kbl[4];
                    ldmx4(kbh, &sKH[(ntp * 16 + brow_base) * ASTR + kk * 16 + bcol]);
                    ldmx4(kbl, &sKL[(ntp * 16 + brow_base) * ASTR + kk * 16 + bcol]);
#pragma unroll
                    for (int mt = 0; mt < 2; mt++) {
                        mma_f16(sS[mt][2 * ntp],     qh[mt][kk], kbh);
                        mma_f16(sS[mt][2 * ntp],     qh[mt][kk], kbl);
                        mma_f16(sS[mt][2 * ntp],     ql[mt][kk], kbh);
                        mma_f16(sS[mt][2 * ntp + 1], qh[mt][kk], kbh + 2);
                        mma_f16(sS[mt][2 * ntp + 1], qh[mt][kk], kbl + 2);
                        mma_f16(sS[mt][2 * ntp + 1], ql[mt][kk], kbh + 2);
                    }
                }
            }
        }

        if (kt >= 2 * qt) {
#pragma unroll
            for (int mt = 0; mt < 2; mt++)
#pragma unroll
                for (int nt = 0; nt < 8; nt++)
#pragma unroll
                    for (int c = 0; c < 4; c++) {
                        int colg = kt * 64 + nt * 8 + 2 * tg + (c & 1);
                        int rowg = q0 + m0 + mt * 16 + g + ((c >> 1) & 1) * 8;
                        if (colg > rowg) sS[mt][nt][c] = -1e30f;
                    }
        }

        float corr[2][2];
#pragma unroll
        for (int mt = 0; mt < 2; mt++)
#pragma unroll
            for (int rr = 0; rr < 2; rr++) {
                float mx = -1e30f;
#pragma unroll
                for (int nt = 0; nt < 8; nt++)
                    mx = fmaxf(mx, fmaxf(sS[mt][nt][2 * rr], sS[mt][nt][2 * rr + 1]));
                mx = fmaxf(mx, __shfl_xor_sync(0xffffffffu, mx, 1));
                mx = fmaxf(mx, __shfl_xor_sync(0xffffffffu, mx, 2));
                float mn = fmaxf(mrow[mt][rr], mx);
                corr[mt][rr] = __expf(mrow[mt][rr] - mn);
                float lt = 0.f;
#pragma unroll
                for (int nt = 0; nt < 8; nt++) {
                    float e0 = __expf(sS[mt][nt][2 * rr]     - mn);
                    float e1 = __expf(sS[mt][nt][2 * rr + 1] - mn);
                    sS[mt][nt][2 * rr] = e0; sS[mt][nt][2 * rr + 1] = e1;
                    lt += e0 + e1;
                }
                lt += __shfl_xor_sync(0xffffffffu, lt, 1);
                lt += __shfl_xor_sync(0xffffffffu, lt, 2);
                lrow[mt][rr] = lrow[mt][rr] * corr[mt][rr] + lt;
                mrow[mt][rr] = mn;
            }
#pragma unroll
        for (int mt = 0; mt < 2; mt++)
#pragma unroll
            for (int nt = 0; nt < 8; nt++) {
                oO[mt][nt][0] *= corr[mt][0]; oO[mt][nt][1] *= corr[mt][0];
                oO[mt][nt][2] *= corr[mt][1]; oO[mt][nt][3] *= corr[mt][1];
            }

        // ---- O += P V  (fp16 2-product: Ph*Vh + Ph*Vl) ----
        {
            int vrow_base = (lane & 15);
            int vcol = (lane >> 4) * 8;
#pragma unroll
            for (int kk2 = 0; kk2 < 4; kk2++) {
                unsigned aPh[2][4];
#pragma unroll
                for (int mt = 0; mt < 2; mt++)
#pragma unroll
                    for (int half = 0; half < 2; half++) {
                        int nt = 2 * kk2 + half;
                        __half h0 = __float2half(sS[mt][nt][0]);
                        __half h1 = __float2half(sS[mt][nt][1]);
                        __half h2 = __float2half(sS[mt][nt][2]);
                        __half h3 = __float2half(sS[mt][nt][3]);
                        aPh[mt][2 * half]     = pkh(h0, h1);
                        aPh[mt][2 * half + 1] = pkh(h2, h3);
                    }
#pragma unroll
                for (int dtp = 0; dtp < 4; dtp++) {
                    unsigned vbh[4], vbl[4];
                    ldmx4t(vbh, &sVH[(kk2 * 16 + vrow_base) * ASTR + dtp * 16 + vcol]);
                    ldmx4t(vbl, &sVL[(kk2 * 16 + vrow_base) * ASTR + dtp * 16 + vcol]);
#pragma unroll
                    for (int mt = 0; mt < 2; mt++) {
                        mma_f16(oO[mt][2 * dtp],     aPh[mt], vbh);
                        mma_f16(oO[mt][2 * dtp],     aPh[mt], vbl);
                        mma_f16(oO[mt][2 * dtp + 1], aPh[mt], vbh + 2);
                        mma_f16(oO[mt][2 * dtp + 1], aPh[mt], vbl + 2);
                    }
                }
            }
        }
        __syncthreads();
    }

#pragma unroll
    for (int mt = 0; mt < 2; mt++) {
        float inv0 = 1.0f / lrow[mt][0];
        float inv1 = 1.0f / lrow[mt][1];
#pragma unroll
        for (int nt = 0; nt < 8; nt++) {
            int col = h * HD + nt * 8 + 2 * tg;
            size_t off0 = (size_t)(b * SS + q0 + m0 + mt * 16 + g) * DD + col;
            size_t off1 = off0 + (size_t)8 * DD;
            split_store(g_Ah, g_Al, off0, oO[mt][nt][0] * inv0, oO[mt][nt][1] * inv0);
            split_store(g_Ah, g_Al, off1, oO[mt][nt][2] * inv1, oO[mt][nt][3] * inv1);
        }
    }
}

// ---------------------------------------------------------------------------
extern "C" void kernel_launch(void* const* d_in, const int* in_sizes, int n_in,
                              void* d_out, int out_size)
{
    const float* x   = (const float*)d_in[0];
    const float* fco = (const float*)d_in[1];
    const float* fsi = (const float*)d_in[2];
    const float* wq  = (const float*)d_in[3];
    const float* wk  = (const float*)d_in[4];
    const float* wv  = (const float*)d_in[5];
    const float* wo  = (const float*)d_in[6];
    float* out = (float*)d_out;

    cudaFuncSetAttribute(gemm_mma, cudaFuncAttributeMaxDynamicSharedMemorySize, GEMM_SMEM);

    // split x; transpose+split weights (merged QKV + wo)
    cvt_kernel<<<(BS * DD + 255) / 256, 256>>>(x, BS * DD);
    wtr_kernel<<<dim3(DD / 32, DD / 32), dim3(32, 8)>>>(wq, 0, 0, DD);
    wtr_kernel<<<dim3(KVD / 32, DD / 32), dim3(32, 8)>>>(wk, DD, 0, KVD);
    wtr_kernel<<<dim3(KVD / 32, DD / 32), dim3(32, 8)>>>(wv, DD + KVD, 0, KVD);
    wtr_kernel<<<dim3(DD / 32, DD / 32), dim3(32, 8)>>>(wo, 0, 1, DD);

    // merged QKV projection with fused RoPE + fp16-split epilogue
    gemm_mma<<<dim3(NQKV / 128, BS / 128), 128, GEMM_SMEM>>>(0, 0, nullptr, 0, fco, fsi);

    // attention (128 q-rows per CTA)
    attn_mma_kernel<<<dim3(SS / 128, NH, BB), 128>>>();

    // output projection (fp32 epilogue -> out, 2-product)
    gemm_mma<<<dim3(DD / 128, BS / 128), 128, GEMM_SMEM>>>(1, 1, out, 1, fco, fsi);
}

// round 12
// speedup vs baseline: 1.4580x; 1.2873x over previous
#include <cuda_runtime.h>
#include <cuda_fp16.h>
#include <math.h>
#include <stdint.h>

#define BB 2
#define SS 2048
#define DD 2048
#define NH 32
#define NKV 8
#define HD 64
#define KVD (NKV*HD)   /* 512 */
#define BS (BB*SS)     /* 4096 */
#define NQKV (DD + 2*KVD)  /* 3072 */

// fp16 scratch. A-side operands are hi-only; K/V keep hi/lo splits (B-side of S/PV).
__device__ __half g_xh[BS*DD];
__device__ __half g_Ah[BS*DD];
__device__ __half g_Qh[BS*DD];
__device__ __half g_Kh[BS*KVD], g_Kl[BS*KVD];
__device__ __half g_Vh[BS*KVD], g_Vl[BS*KVD];
// transposed weight splits: merged [3072 x 2048] for QKV, [2048 x 2048] for O
__device__ __half g_wTh[NQKV*DD], g_wTl[NQKV*DD];
__device__ __half g_woTh[DD*DD],  g_woTl[DD*DD];

// ---------------------------------------------------------------------------
// helpers
// ---------------------------------------------------------------------------
__device__ __forceinline__ uint32_t smem_u32(const void* p) {
    uint32_t a;
    asm("{ .reg .u64 t; cvta.to.shared.u64 t, %1; cvt.u32.u64 %0, t; }"
        : "=r"(a) : "l"(p));
    return a;
}

__device__ __forceinline__ unsigned pkh(__half a, __half b)
{
    return (unsigned)__half_as_ushort(a) | ((unsigned)__half_as_ushort(b) << 16);
}

__device__ __forceinline__ void mma_f16(float* c, const unsigned* a, const unsigned* b)
{
    asm volatile(
        "mma.sync.aligned.m16n8k16.row.col.f32.f16.f16.f32 "
        "{%0,%1,%2,%3}, {%4,%5,%6,%7}, {%8,%9}, {%0,%1,%2,%3};\n"
        : "+f"(c[0]), "+f"(c[1]), "+f"(c[2]), "+f"(c[3])
        : "r"(a[0]), "r"(a[1]), "r"(a[2]), "r"(a[3]), "r"(b[0]), "r"(b[1]));
}

__device__ __forceinline__ void ldmx4(unsigned* r, const __half* p)
{
    unsigned a = smem_u32(p);
    asm volatile("ldmatrix.sync.aligned.m8n8.x4.shared.b16 {%0,%1,%2,%3}, [%4];"
                 : "=r"(r[0]), "=r"(r[1]), "=r"(r[2]), "=r"(r[3]) : "r"(a));
}
__device__ __forceinline__ void ldmx4t(unsigned* r, const __half* p)
{
    unsigned a = smem_u32(p);
    asm volatile("ldmatrix.sync.aligned.m8n8.x4.trans.shared.b16 {%0,%1,%2,%3}, [%4];"
                 : "=r"(r[0]), "=r"(r[1]), "=r"(r[2]), "=r"(r[3]) : "r"(a));
}

// split fp32 -> fp16 hi/lo pair packed stores
__device__ __forceinline__ void split_store(__half* bh, __half* bl,
                                            size_t off, float f0, float f1)
{
    __half h0 = __float2half(f0), h1 = __float2half(f1);
    *(unsigned*)(bh + off) = pkh(h0, h1);
    __half l0 = __float2half(f0 - __half2float(h0));
    __half l1 = __float2half(f1 - __half2float(h1));
    *(unsigned*)(bl + off) = pkh(l0, l1);
}

// ---------------------------------------------------------------------------
// fp32 x -> fp16 hi only
// ---------------------------------------------------------------------------
__global__ void cvt_kernel(const float* __restrict__ src, int n)
{
    int i = blockIdx.x * blockDim.x + threadIdx.x;
    if (i >= n) return;
    g_xh[i] = __float2half(src[i]);
}

// ---------------------------------------------------------------------------
// Weight transpose + split. wsel 0: merged QKV (wq|wk|wv) -> g_wT rows [0,3072)
// wsel 1: wo -> g_woT. Grid x covers output rows / 32.
// ---------------------------------------------------------------------------
__global__ void wtr_kernel(const float* __restrict__ w0, const float* __restrict__ w1,
                           const float* __restrict__ w2, int wsel)
{
    __shared__ float t[32][33];
    int n0 = blockIdx.x * 32, k0 = blockIdx.y * 32;
    const float* w; int N; int ncol;
    __half *ph, *pl;
    if (wsel) {
        w = w0; N = DD; ncol = n0; ph = g_woTh; pl = g_woTl;
    } else if (n0 < DD) {
        w = w0; N = DD;  ncol = n0;            ph = g_wTh; pl = g_wTl;
    } else if (n0 < DD + KVD) {
        w = w1; N = KVD; ncol = n0 - DD;       ph = g_wTh; pl = g_wTl;
    } else {
        w = w2; N = KVD; ncol = n0 - DD - KVD; ph = g_wTh; pl = g_wTl;
    }
    int tx = threadIdx.x, ty = threadIdx.y;
#pragma unroll
    for (int yy = 0; yy < 4; yy++) {
        int k = k0 + ty + yy * 8;
        t[ty + yy * 8][tx] = w[(size_t)k * N + ncol + tx];
    }
    __syncthreads();
#pragma unroll
    for (int yy = 0; yy < 4; yy++) {
        int n = n0 + ty + yy * 8;
        float v = t[tx][ty + yy * 8];
        __half hi = __float2half(v);
        __half lo = __float2half(v - __half2float(hi));
        ph[(size_t)n * DD + k0 + tx] = hi;
        pl[(size_t)n * DD + k0 + tx] = lo;
    }
}

// ---------------------------------------------------------------------------
// fp16 2-product GEMM: C = Ah @ (Bh+Bl)^T. 128x128 CTA, 4 warps (64x64 each),
// BK=32, cp.async double buffer. 3 smem matrices per stage (Ah, Bh, Bl).
// ---------------------------------------------------------------------------
#define GSTR 40
#define GMAT (128*GSTR*2)             /* 10240 B per matrix */
#define GSTAGE (3*GMAT)               /* 30720 */
#define GEMM_SMEM (2*GSTAGE)          /* 61440 */

__global__ __launch_bounds__(128) void gemm_mma(int asel, int bsel,
                                                float* Cext, int osel,
                                                const float* __restrict__ fcos,
                                                const float* __restrict__ fsin)
{
    extern __shared__ char dsm[];
    const int K = DD;

    const __half* Ah = asel ? g_Ah : g_xh;
    const __half* Bh = bsel ? g_woTh : g_wTh;
    const __half* Bl = bsel ? g_woTl : g_wTl;

    const int tid  = threadIdx.x;
    const int lane = tid & 31;
    const int wid  = tid >> 5;
    const int g    = lane >> 2;
    const int tg   = lane & 3;
    const int warpM = (wid >> 1) * 64;
    const int warpN = (wid & 1) * 64;
    const int bm = blockIdx.y * 128;
    const int bn = blockIdx.x * 128;

    const __half* srcs[3] = {Ah, Bh, Bl};

    float acc[4][8][4];
#pragma unroll
    for (int a = 0; a < 4; a++)
#pragma unroll
        for (int b = 0; b < 8; b++)
#pragma unroll
            for (int c = 0; c < 4; c++) acc[a][b][c] = 0.f;

    auto docopy = [&](int ch) {
        const uint32_t sb = smem_u32(dsm) + (ch & 1) * GSTAGE;
#pragma unroll
        for (int it = 0; it < 12; it++) {
            int o = tid + it * 128;          // 0..1535
            int mat = o >> 9;                // 0=Ah 1=Bh 2=Bl
            int idx = o & 511;
            int r = idx >> 2, c8 = (idx & 3) * 8;
            int rowbase = (mat == 0) ? bm : bn;
            uint32_t so = sb + mat * GMAT + r * (GSTR * 2) + c8 * 2;
            const __half* gp = srcs[mat] + (size_t)(rowbase + r) * K + ch * 32 + c8;
            asm volatile("cp.async.cg.shared.global [%0], [%1], 16;\n"
                         :: "r"(so), "l"(gp));
        }
        asm volatile("cp.async.commit_group;\n");
    };

    const int nkb = K / 32;
    docopy(0);

    for (int kb = 0; kb < nkb; kb++) {
        if (kb + 1 < nkb) {
            docopy(kb + 1);
            asm volatile("cp.async.wait_group 1;\n" ::: "memory");
        } else {
            asm volatile("cp.async.wait_group 0;\n" ::: "memory");
        }
        __syncthreads();

        const __half* sAh = (const __half*)(dsm + (kb & 1) * GSTAGE);
        const __half* sBh = sAh + 128 * GSTR;
        const __half* sBl = sBh + 128 * GSTR;

#pragma unroll
        for (int ks = 0; ks < 2; ks++) {
            const int kc = ks * 16;
            unsigned ah[4][4];
            {
                int arow = warpM + (lane & 15);
                int acol = kc + (lane >> 4) * 8;
#pragma unroll
                for (int mt = 0; mt < 4; mt++)
                    ldmx4(ah[mt], &sAh[(arow + mt * 16) * GSTR + acol]);
            }
            unsigned bh[4][4], bl[4][4];
            {
                int brow = (lane & 7) + ((lane >> 4) & 1) * 8;
                int bcol = kc + ((lane >> 3) & 1) * 8;
#pragma unroll
                for (int ng = 0; ng < 4; ng++) {
                    ldmx4(bh[ng], &sBh[(warpN + ng * 16 + brow) * GSTR + bcol]);
                    ldmx4(bl[ng], &sBl[(warpN + ng * 16 + brow) * GSTR + bcol]);
                }
            }
#pragma unroll
            for (int mt = 0; mt < 4; mt++)
#pragma unroll
                for (int ng = 0; ng < 4; ng++) {
                    mma_f16(acc[mt][2 * ng],     ah[mt], bh[ng]);
                    mma_f16(acc[mt][2 * ng],     ah[mt], bl[ng]);
                    mma_f16(acc[mt][2 * ng + 1], ah[mt], bh[ng] + 2);
                    mma_f16(acc[mt][2 * ng + 1], ah[mt], bl[ng] + 2);
                }
        }
        __syncthreads();
    }

    if (osel == 1) {
#pragma unroll
        for (int mt = 0; mt < 4; mt++)
#pragma unroll
            for (int nt = 0; nt < 8; nt++) {
                int row = bm + warpM + mt * 16 + g;
                int col = bn + warpN + nt * 8 + tg * 2;
                *(float2*)&Cext[(size_t)row * DD + col] =
                    make_float2(acc[mt][nt][0], acc[mt][nt][1]);
                *(float2*)&Cext[(size_t)(row + 8) * DD + col] =
                    make_float2(acc[mt][nt][2], acc[mt][nt][3]);
            }
        return;
    }

    // fused RoPE + store epilogue (QKV gemm). Segment is CTA-uniform.
    const int seg = (bn < DD) ? 0 : (bn < DD + KVD) ? 1 : 2;
#pragma unroll
    for (int mt = 0; mt < 4; mt++) {
        int row0 = bm + warpM + mt * 16 + g;
#pragma unroll
        for (int nt = 0; nt < 8; nt++) {
            int col = bn + warpN + nt * 8 + tg * 2;
            float a0 = acc[mt][nt][0], a1 = acc[mt][nt][1];
            float a2 = acc[mt][nt][2], a3 = acc[mt][nt][3];
            if (seg == 2) {
                size_t off0 = (size_t)row0 * KVD + (col - DD - KVD);
                split_store(g_Vh, g_Vl, off0, a0, a1);
                split_store(g_Vh, g_Vl, off0 + 8 * KVD, a2, a3);
            } else {
                int p = (col & 63) >> 1;
                int s0 = row0 & (SS - 1);
                int s1 = (row0 + 8) & (SS - 1);
                float c0 = fcos[s0 * 32 + p], sn0 = fsin[s0 * 32 + p];
                float c1 = fcos[s1 * 32 + p], sn1 = fsin[s1 * 32 + p];
                float r0 = a0 * c0 - a1 * sn0;
                float r1 = a0 * sn0 + a1 * c0;
                float r2 = a2 * c1 - a3 * sn1;
                float r3 = a2 * sn1 + a3 * c1;
                if (seg == 0) {
                    // Q: scale by 1/8; hi-only store
                    size_t off0 = (size_t)row0 * DD + col;
                    *(unsigned*)(g_Qh + off0) =
                        pkh(__float2half(r0 * 0.125f), __float2half(r1 * 0.125f));
                    *(unsigned*)(g_Qh + off0 + 8 * DD) =
                        pkh(__float2half(r2 * 0.125f), __float2half(r3 * 0.125f));
                } else {
                    size_t off0 = (size_t)row0 * KVD + (col - DD);
                    split_store(g_Kh, g_Kl, off0, r0, r1);
                    split_store(g_Kh, g_Kl, off0 + 8 * KVD, r2, r3);
                }
            }
        }
    }
}

// ---------------------------------------------------------------------------
// Causal flash attention. S = Qh*(Kh+Kl) (2 products). O += Ph*(Vh+Vl).
// CTA: 128 q-rows x 64 kv; 4 warps x 32 q-rows.
// ---------------------------------------------------------------------------
#define ASTR 72
#define AROWS (64*ASTR)

__global__ __launch_bounds__(128) void attn_mma_kernel()
{
    __shared__ __half sm[4 * AROWS];

    const int qt = gridDim.x - 1 - blockIdx.x;
    const int h  = blockIdx.y;
    const int b  = blockIdx.z;
    const int hk = h >> 2;
    const int tid  = threadIdx.x;
    const int lane = tid & 31;
    const int wid  = tid >> 5;
    const int g    = lane >> 2;
    const int tg   = lane & 3;
    const int m0   = wid * 32;
    const int q0   = qt * 128;

    // stage Q hi (128 rows) into sm[0 .. 2*AROWS)
#pragma unroll
    for (int it = 0; it < 8; it++) {
        int lin = tid + it * 128;          // 0..1023 uint4
        int r = lin >> 3, d8 = (lin & 7) * 8;
        size_t gb = (size_t)(b * SS + q0 + r) * DD + h * HD + d8;
        *(uint4*)&sm[r * ASTR + d8] = *(const uint4*)(g_Qh + gb);
    }
    __syncthreads();

    unsigned qh[2][4][4];
#pragma unroll
    for (int mt = 0; mt < 2; mt++) {
        int arow = m0 + mt * 16 + (lane & 15);
#pragma unroll
        for (int kk = 0; kk < 4; kk++) {
            int acol = kk * 16 + (lane >> 4) * 8;
            ldmx4(qh[mt][kk], &sm[arow * ASTR + acol]);
        }
    }
    __syncthreads();

    __half* sKH = sm;
    __half* sKL = sm + AROWS;
    __half* sVH = sm + 2 * AROWS;
    __half* sVL = sm + 3 * AROWS;

    float oO[2][8][4];
#pragma unroll
    for (int mt = 0; mt < 2; mt++)
#pragma unroll
        for (int i = 0; i < 8; i++)
#pragma unroll
            for (int c = 0; c < 4; c++) oO[mt][i][c] = 0.f;
    float mrow[2][2] = {{-1e30f, -1e30f}, {-1e30f, -1e30f}};
    float lrow[2][2] = {{0.f, 0.f}, {0.f, 0.f}};

    const int nkt = 2 * qt + 2;
    for (int kt = 0; kt < nkt; kt++) {
#pragma unroll
        for (int it = 0; it < 4; it++) {
            int lin = tid + it * 128;
            int r = lin >> 3, d8 = (lin & 7) * 8;
            size_t gb = (size_t)(b * SS + kt * 64 + r) * KVD + hk * HD + d8;
            *(uint4*)&sKH[r * ASTR + d8] = *(const uint4*)(g_Kh + gb);
            *(uint4*)&sKL[r * ASTR + d8] = *(const uint4*)(g_Kl + gb);
            *(uint4*)&sVH[r * ASTR + d8] = *(const uint4*)(g_Vh + gb);
            *(uint4*)&sVL[r * ASTR + d8] = *(const uint4*)(g_Vl + gb);
        }
        __syncthreads();

        float sS[2][8][4];
#pragma unroll
        for (int mt = 0; mt < 2; mt++)
#pragma unroll
            for (int i = 0; i < 8; i++)
#pragma unroll
                for (int c = 0; c < 4; c++) sS[mt][i][c] = 0.f;

        {
            int brow_base = (lane & 7) + ((lane >> 4) & 1) * 8;
            int bcol = ((lane >> 3) & 1) * 8;
#pragma unroll
            for (int kk = 0; kk < 4; kk++) {
#pragma unroll
                for (int ntp = 0; ntp < 4; ntp++) {
                    unsigned kbh[4], kbl[4];
                    ldmx4(kbh, &sKH[(ntp * 16 + brow_base) * ASTR + kk * 16 + bcol]);
                    ldmx4(kbl, &sKL[(ntp * 16 + brow_base) * ASTR + kk * 16 + bcol]);
#pragma unroll
                    for (int mt = 0; mt < 2; mt++) {
                        mma_f16(sS[mt][2 * ntp],     qh[mt][kk], kbh);
                        mma_f16(sS[mt][2 * ntp],     qh[mt][kk], kbl);
                        mma_f16(sS[mt][2 * ntp + 1], qh[mt][kk], kbh + 2);
                        mma_f16(sS[mt][2 * ntp + 1], qh[mt][kk], kbl + 2);
                    }
                }
            }
        }

        if (kt >= 2 * qt) {
#pragma unroll
            for (int mt = 0; mt < 2; mt++)
#pragma unroll
                for (int nt = 0; nt < 8; nt++)
#pragma unroll
                    for (int c = 0; c < 4; c++) {
                        int colg = kt * 64 + nt * 8 + 2 * tg + (c & 1);
                        int rowg = q0 + m0 + mt * 16 + g + ((c >> 1) & 1) * 8;
                        if (colg > rowg) sS[mt][nt][c] = -1e30f;
                    }
        }

        float corr[2][2];
#pragma unroll
        for (int mt = 0; mt < 2; mt++)
#pragma unroll
            for (int rr = 0; rr < 2; rr++) {
                float mx = -1e30f;
#pragma unroll
                for (int nt = 0; nt < 8; nt++)
                    mx = fmaxf(mx, fmaxf(sS[mt][nt][2 * rr], sS[mt][nt][2 * rr + 1]));
                mx = fmaxf(mx, __shfl_xor_sync(0xffffffffu, mx, 1));
                mx = fmaxf(mx, __shfl_xor_sync(0xffffffffu, mx, 2));
                float mn = fmaxf(mrow[mt][rr], mx);
                corr[mt][rr] = __expf(mrow[mt][rr] - mn);
                float lt = 0.f;
#pragma unroll
                for (int nt = 0; nt < 8; nt++) {
                    float e0 = __expf(sS[mt][nt][2 * rr]     - mn);
                    float e1 = __expf(sS[mt][nt][2 * rr + 1] - mn);
                    sS[mt][nt][2 * rr] = e0; sS[mt][nt][2 * rr + 1] = e1;
                    lt += e0 + e1;
                }
                lt += __shfl_xor_sync(0xffffffffu, lt, 1);
                lt += __shfl_xor_sync(0xffffffffu, lt, 2);
                lrow[mt][rr] = lrow[mt][rr] * corr[mt][rr] + lt;
                mrow[mt][rr] = mn;
            }
#pragma unroll
        for (int mt = 0; mt < 2; mt++)
#pragma unroll
            for (int nt = 0; nt < 8; nt++) {
                oO[mt][nt][0] *= corr[mt][0]; oO[mt][nt][1] *= corr[mt][0];
                oO[mt][nt][2] *= corr[mt][1]; oO[mt][nt][3] *= corr[mt][1];
            }

        // O += P V  (Ph * (Vh + Vl))
        {
            int vrow_base = (lane & 15);
            int vcol = (lane >> 4) * 8;
#pragma unroll
            for (int kk2 = 0; kk2 < 4; kk2++) {
                unsigned aPh[2][4];
#pragma unroll
                for (int mt = 0; mt < 2; mt++)
#pragma unroll
                    for (int half = 0; half < 2; half++) {
                        int nt = 2 * kk2 + half;
                        aPh[mt][2 * half] = pkh(__float2half(sS[mt][nt][0]),
                                                __float2half(sS[mt][nt][1]));
                        aPh[mt][2 * half + 1] = pkh(__float2half(sS[mt][nt][2]),
                                                    __float2half(sS[mt][nt][3]));
                    }
#pragma unroll
                for (int dtp = 0; dtp < 4; dtp++) {
                    unsigned vbh[4], vbl[4];
                    ldmx4t(vbh, &sVH[(kk2 * 16 + vrow_base) * ASTR + dtp * 16 + vcol]);
                    ldmx4t(vbl, &sVL[(kk2 * 16 + vrow_base) * ASTR + dtp * 16 + vcol]);
#pragma unroll
                    for (int mt = 0; mt < 2; mt++) {
                        mma_f16(oO[mt][2 * dtp],     aPh[mt], vbh);
                        mma_f16(oO[mt][2 * dtp],     aPh[mt], vbl);
                        mma_f16(oO[mt][2 * dtp + 1], aPh[mt], vbh + 2);
                        mma_f16(oO[mt][2 * dtp + 1], aPh[mt], vbl + 2);
                    }
                }
            }
        }
        __syncthreads();
    }

    // epilogue: hi-only store to g_Ah
#pragma unroll
    for (int mt = 0; mt < 2; mt++) {
        float inv0 = 1.0f / lrow[mt][0];
        float inv1 = 1.0f / lrow[mt][1];
#pragma unroll
        for (int nt = 0; nt < 8; nt++) {
            int col = h * HD + nt * 8 + 2 * tg;
            size_t off0 = (size_t)(b * SS + q0 + m0 + mt * 16 + g) * DD + col;
            size_t off1 = off0 + (size_t)8 * DD;
            *(unsigned*)(g_Ah + off0) = pkh(__float2half(oO[mt][nt][0] * inv0),
                                            __float2half(oO[mt][nt][1] * inv0));
            *(unsigned*)(g_Ah + off1) = pkh(__float2half(oO[mt][nt][2] * inv1),
                                            __float2half(oO[mt][nt][3] * inv1));
        }
    }
}

// ---------------------------------------------------------------------------
extern "C" void kernel_launch(void* const* d_in, const int* in_sizes, int n_in,
                              void* d_out, int out_size)
{
    const float* x   = (const float*)d_in[0];
    const float* fco = (const float*)d_in[1];
    const float* fsi = (const float*)d_in[2];
    const float* wq  = (const float*)d_in[3];
    const float* wk  = (const float*)d_in[4];
    const float* wv  = (const float*)d_in[5];
    const float* wo  = (const float*)d_in[6];
    float* out = (float*)d_out;

    cudaFuncSetAttribute(gemm_mma, cudaFuncAttributeMaxDynamicSharedMemorySize, GEMM_SMEM);

    // convert x (hi only); transpose+split weights (merged QKV + wo)
    cvt_kernel<<<(BS * DD + 255) / 256, 256>>>(x, BS * DD);
    wtr_kernel<<<dim3(NQKV / 32, DD / 32), dim3(32, 8)>>>(wq, wk, wv, 0);
    wtr_kernel<<<dim3(DD / 32, DD / 32), dim3(32, 8)>>>(wo, wo, wo, 1);

    // merged QKV projection with fused RoPE epilogue
    gemm_mma<<<dim3(NQKV / 128, BS / 128), 128, GEMM_SMEM>>>(0, 0, nullptr, 0, fco, fsi);

    // attention (128 q-rows per CTA)
    attn_mma_kernel<<<dim3(SS / 128, NH, BB), 128>>>();

    // output projection (fp32 epilogue -> out)
    gemm_mma<<<dim3(DD / 128, BS / 128), 128, GEMM_SMEM>>>(1, 1, out, 1, fco, fsi);
}

// round 15
// speedup vs baseline: 1.4979x; 1.0273x over previous
#include <cuda_runtime.h>
#include <cuda_fp16.h>
#include <math.h>
#include <stdint.h>

#define BB 2
#define SS 2048
#define DD 2048
#define NH 32
#define NKV 8
#define HD 64
#define KVD (NKV*HD)   /* 512 */
#define BS (BB*SS)     /* 4096 */
#define NQKV (DD + 2*KVD)  /* 3072 */

// fp16 scratch. A-side operands are hi-only; K/V keep hi/lo splits.
__device__ __half g_xh[BS*DD];
__device__ __half g_Ah[BS*DD];
__device__ __half g_Qh[BS*DD];
__device__ __half g_Kh[BS*KVD], g_Kl[BS*KVD];
__device__ __half g_Vh[BS*KVD], g_Vl[BS*KVD];
// transposed weight splits: merged [3072 x 2048] for QKV, [2048 x 2048] for O
__device__ __half g_wTh[NQKV*DD], g_wTl[NQKV*DD];
__device__ __half g_woTh[DD*DD],  g_woTl[DD*DD];

// ---------------------------------------------------------------------------
// helpers
// ---------------------------------------------------------------------------
__device__ __forceinline__ uint32_t smem_u32(const void* p) {
    uint32_t a;
    asm("{ .reg .u64 t; cvta.to.shared.u64 t, %1; cvt.u32.u64 %0, t; }"
        : "=r"(a) : "l"(p));
    return a;
}

__device__ __forceinline__ unsigned pkh(__half a, __half b)
{
    return (unsigned)__half_as_ushort(a) | ((unsigned)__half_as_ushort(b) << 16);
}

__device__ __forceinline__ void mma_f16(float* c, const unsigned* a, const unsigned* b)
{
    asm volatile(
        "mma.sync.aligned.m16n8k16.row.col.f32.f16.f16.f32 "
        "{%0,%1,%2,%3}, {%4,%5,%6,%7}, {%8,%9}, {%0,%1,%2,%3};\n"
        : "+f"(c[0]), "+f"(c[1]), "+f"(c[2]), "+f"(c[3])
        : "r"(a[0]), "r"(a[1]), "r"(a[2]), "r"(a[3]), "r"(b[0]), "r"(b[1]));
}

__device__ __forceinline__ void ldmx4(unsigned* r, const __half* p)
{
    unsigned a = smem_u32(p);
    asm volatile("ldmatrix.sync.aligned.m8n8.x4.shared.b16 {%0,%1,%2,%3}, [%4];"
                 : "=r"(r[0]), "=r"(r[1]), "=r"(r[2]), "=r"(r[3]) : "r"(a));
}
__device__ __forceinline__ void ldmx4t(unsigned* r, const __half* p)
{
    unsigned a = smem_u32(p);
    asm volatile("ldmatrix.sync.aligned.m8n8.x4.trans.shared.b16 {%0,%1,%2,%3}, [%4];"
                 : "=r"(r[0]), "=r"(r[1]), "=r"(r[2]), "=r"(r[3]) : "r"(a));
}

// split fp32 -> fp16 hi/lo pair packed stores
__device__ __forceinline__ void split_store(__half* bh, __half* bl,
                                            size_t off, float f0, float f1)
{
    __half h0 = __float2half(f0), h1 = __float2half(f1);
    *(unsigned*)(bh + off) = pkh(h0, h1);
    __half l0 = __float2half(f0 - __half2float(h0));
    __half l1 = __float2half(f1 - __half2float(h1));
    *(unsigned*)(bl + off) = pkh(l0, l1);
}

// ---------------------------------------------------------------------------
// fp32 x -> fp16 hi only
// ---------------------------------------------------------------------------
__global__ void cvt_kernel(const float* __restrict__ src, int n)
{
    int i = blockIdx.x * blockDim.x + threadIdx.x;
    if (i >= n) return;
    g_xh[i] = __float2half(src[i]);
}

// ---------------------------------------------------------------------------
// Weight transpose + split. wsel 0: merged QKV (wq|wk|wv) -> g_wT rows [0,3072)
// wsel 1: wo -> g_woT.
// ---------------------------------------------------------------------------
__global__ void wtr_kernel(const float* __restrict__ w0, const float* __restrict__ w1,
                           const float* __restrict__ w2, int wsel)
{
    __shared__ float t[32][33];
    int n0 = blockIdx.x * 32, k0 = blockIdx.y * 32;
    const float* w; int N; int ncol;
    __half *ph, *pl;
    if (wsel) {
        w = w0; N = DD; ncol = n0; ph = g_woTh; pl = g_woTl;
    } else if (n0 < DD) {
        w = w0; N = DD;  ncol = n0;            ph = g_wTh; pl = g_wTl;
    } else if (n0 < DD + KVD) {
        w = w1; N = KVD; ncol = n0 - DD;       ph = g_wTh; pl = g_wTl;
    } else {
        w = w2; N = KVD; ncol = n0 - DD - KVD; ph = g_wTh; pl = g_wTl;
    }
    int tx = threadIdx.x, ty = threadIdx.y;
#pragma unroll
    for (int yy = 0; yy < 4; yy++) {
        int k = k0 + ty + yy * 8;
        t[ty + yy * 8][tx] = w[(size_t)k * N + ncol + tx];
    }
    __syncthreads();
#pragma unroll
    for (int yy = 0; yy < 4; yy++) {
        int n = n0 + ty + yy * 8;
        float v = t[tx][ty + yy * 8];
        __half hi = __float2half(v);
        __half lo = __float2half(v - __half2float(hi));
        ph[(size_t)n * DD + k0 + tx] = hi;
        pl[(size_t)n * DD + k0 + tx] = lo;
    }
}

// ---------------------------------------------------------------------------
// fp16 2-product GEMM: C = Ah @ (Bh+Bl)^T. 128x128 CTA, 4 warps (64x64 each),
// BK=32, cp.async double buffer. MMA issue in two passes (all-h then all-l)
// so consecutive MMAs never share an accumulator (RAW distance 32).
// ---------------------------------------------------------------------------
#define GSTR 40
#define GMAT (128*GSTR*2)             /* 10240 B per matrix */
#define GSTAGE (3*GMAT)               /* 30720 */
#define GEMM_SMEM (2*GSTAGE)          /* 61440 */

__global__ __launch_bounds__(128) void gemm_mma(int asel, int bsel,
                                                float* Cext, int osel,
                                                const float* __restrict__ fcos,
                                                const float* __restrict__ fsin)
{
    extern __shared__ char dsm[];
    const int K = DD;

    const __half* Ah = asel ? g_Ah : g_xh;
    const __half* Bh = bsel ? g_woTh : g_wTh;
    const __half* Bl = bsel ? g_woTl : g_wTl;

    const int tid  = threadIdx.x;
    const int lane = tid & 31;
    const int wid  = tid >> 5;
    const int g    = lane >> 2;
    const int tg   = lane & 3;
    const int warpM = (wid >> 1) * 64;
    const int warpN = (wid & 1) * 64;
    const int bm = blockIdx.y * 128;
    const int bn = blockIdx.x * 128;

    const __half* srcs[3] = {Ah, Bh, Bl};

    float acc[4][8][4];
#pragma unroll
    for (int a = 0; a < 4; a++)
#pragma unroll
        for (int b = 0; b < 8; b++)
#pragma unroll
            for (int c = 0; c < 4; c++) acc[a][b][c] = 0.f;

    auto docopy = [&](int ch) {
        const uint32_t sb = smem_u32(dsm) + (ch & 1) * GSTAGE;
#pragma unroll
        for (int it = 0; it < 12; it++) {
            int o = tid + it * 128;
            int mat = o >> 9;
            int idx = o & 511;
            int r = idx >> 2, c8 = (idx & 3) * 8;
            int rowbase = (mat == 0) ? bm : bn;
            uint32_t so = sb + mat * GMAT + r * (GSTR * 2) + c8 * 2;
            const __half* gp = srcs[mat] + (size_t)(rowbase + r) * K + ch * 32 + c8;
            asm volatile("cp.async.cg.shared.global [%0], [%1], 16;\n"
                         :: "r"(so), "l"(gp));
        }
        asm volatile("cp.async.commit_group;\n");
    };

    const int nkb = K / 32;
    docopy(0);

    for (int kb = 0; kb < nkb; kb++) {
        if (kb + 1 < nkb) {
            docopy(kb + 1);
            asm volatile("cp.async.wait_group 1;\n" ::: "memory");
        } else {
            asm volatile("cp.async.wait_group 0;\n" ::: "memory");
        }
        __syncthreads();

        const __half* sAh = (const __half*)(dsm + (kb & 1) * GSTAGE);
        const __half* sBh = sAh + 128 * GSTR;
        const __half* sBl = sBh + 128 * GSTR;

#pragma unroll
        for (int ks = 0; ks < 2; ks++) {
            const int kc = ks * 16;
            unsigned ah[4][4];
            {
                int arow = warpM + (lane & 15);
                int acol = kc + (lane >> 4) * 8;
#pragma unroll
                for (int mt = 0; mt < 4; mt++)
                    ldmx4(ah[mt], &sAh[(arow + mt * 16) * GSTR + acol]);
            }
            unsigned bh[4][4], bl[4][4];
            {
                int brow = (lane & 7) + ((lane >> 4) & 1) * 8;
                int bcol = kc + ((lane >> 3) & 1) * 8;
#pragma unroll
                for (int ng = 0; ng < 4; ng++) {
                    ldmx4(bh[ng], &sBh[(warpN + ng * 16 + brow) * GSTR + bcol]);
                    ldmx4(bl[ng], &sBl[(warpN + ng * 16 + brow) * GSTR + bcol]);
                }
            }
            // pass 1: all hi products (32 MMAs, all distinct accumulators)
#pragma unroll
            for (int mt = 0; mt < 4; mt++)
#pragma unroll
                for (int ng = 0; ng < 4; ng++) {
                    mma_f16(acc[mt][2 * ng],     ah[mt], bh[ng]);
                    mma_f16(acc[mt][2 * ng + 1], ah[mt], bh[ng] + 2);
                }
            // pass 2: all lo products (RAW distance >= 32 from pass 1)
#pragma unroll
            for (int mt = 0; mt < 4; mt++)
#pragma unroll
                for (int ng = 0; ng < 4; ng++) {
                    mma_f16(acc[mt][2 * ng],     ah[mt], bl[ng]);
                    mma_f16(acc[mt][2 * ng + 1], ah[mt], bl[ng] + 2);
                }
        }
        __syncthreads();
    }

    if (osel == 1) {
#pragma unroll
        for (int mt = 0; mt < 4; mt++)
#pragma unroll
            for (int nt = 0; nt < 8; nt++) {
                int row = bm + warpM + mt * 16 + g;
                int col = bn + warpN + nt * 8 + tg * 2;
                *(float2*)&Cext[(size_t)row * DD + col] =
                    make_float2(acc[mt][nt][0], acc[mt][nt][1]);
                *(float2*)&Cext[(size_t)(row + 8) * DD + col] =
                    make_float2(acc[mt][nt][2], acc[mt][nt][3]);
            }
        return;
    }

    // fused RoPE + store epilogue (QKV gemm). Segment is CTA-uniform.
    const int seg = (bn < DD) ? 0 : (bn < DD + KVD) ? 1 : 2;
#pragma unroll
    for (int mt = 0; mt < 4; mt++) {
        int row0 = bm + warpM + mt * 16 + g;
#pragma unroll
        for (int nt = 0; nt < 8; nt++) {
            int col = bn + warpN + nt * 8 + tg * 2;
            float a0 = acc[mt][nt][0], a1 = acc[mt][nt][1];
            float a2 = acc[mt][nt][2], a3 = acc[mt][nt][3];
            if (seg == 2) {
                size_t off0 = (size_t)row0 * KVD + (col - DD - KVD);
                split_store(g_Vh, g_Vl, off0, a0, a1);
                split_store(g_Vh, g_Vl, off0 + 8 * KVD, a2, a3);
            } else {
                int p = (col & 63) >> 1;
                int s0 = row0 & (SS - 1);
                int s1 = (row0 + 8) & (SS - 1);
                float c0 = fcos[s0 * 32 + p], sn0 = fsin[s0 * 32 + p];
                float c1 = fcos[s1 * 32 + p], sn1 = fsin[s1 * 32 + p];
                float r0 = a0 * c0 - a1 * sn0;
                float r1 = a0 * sn0 + a1 * c0;
                float r2 = a2 * c1 - a3 * sn1;
                float r3 = a2 * sn1 + a3 * c1;
                if (seg == 0) {
                    size_t off0 = (size_t)row0 * DD + col;
                    *(unsigned*)(g_Qh + off0) =
                        pkh(__float2half(r0 * 0.125f), __float2half(r1 * 0.125f));
                    *(unsigned*)(g_Qh + off0 + 8 * DD) =
                        pkh(__float2half(r2 * 0.125f), __float2half(r3 * 0.125f));
                } else {
                    size_t off0 = (size_t)row0 * KVD + (col - DD);
                    split_store(g_Kh, g_Kl, off0, r0, r1);
                    split_store(g_Kh, g_Kl, off0 + 8 * KVD, r2, r3);
                }
            }
        }
    }
}

// ---------------------------------------------------------------------------
// Causal flash attention. S = Qh*(Kh+Kl), O += Ph*(Vh+Vl), MMAs issued in
// two passes (h then l) with hoisted fragments for RAW distance.
// CTA: 128 q-rows x 64 kv; 4 warps x 32 q-rows.
// ---------------------------------------------------------------------------
#define ASTR 72
#define AROWS (64*ASTR)

__global__ __launch_bounds__(128) void attn_mma_kernel()
{
    __shared__ __half sm[4 * AROWS];

    const int qt = gridDim.x - 1 - blockIdx.x;
    const int h  = blockIdx.y;
    const int b  = blockIdx.z;
    const int hk = h >> 2;
    const int tid  = threadIdx.x;
    const int lane = tid & 31;
    const int wid  = tid >> 5;
    const int g    = lane >> 2;
    const int tg   = lane & 3;
    const int m0   = wid * 32;
    const int q0   = qt * 128;

#pragma unroll
    for (int it = 0; it < 8; it++) {
        int lin = tid + it * 128;
        int r = lin >> 3, d8 = (lin & 7) * 8;
        size_t gb = (size_t)(b * SS + q0 + r) * DD + h * HD + d8;
        *(uint4*)&sm[r * ASTR + d8] = *(const uint4*)(g_Qh + gb);
    }
    __syncthreads();

    unsigned qh[2][4][4];
#pragma unroll
    for (int mt = 0; mt < 2; mt++) {
        int arow = m0 + mt * 16 + (lane & 15);
#pragma unroll
        for (int kk = 0; kk < 4; kk++) {
            int acol = kk * 16 + (lane >> 4) * 8;
            ldmx4(qh[mt][kk], &sm[arow * ASTR + acol]);
        }
    }
    __syncthreads();

    __half* sKH = sm;
    __half* sKL = sm + AROWS;
    __half* sVH = sm + 2 * AROWS;
    __half* sVL = sm + 3 * AROWS;

    float oO[2][8][4];
#pragma unroll
    for (int mt = 0; mt < 2; mt++)
#pragma unroll
        for (int i = 0; i < 8; i++)
#pragma unroll
            for (int c = 0; c < 4; c++) oO[mt][i][c] = 0.f;
    float mrow[2][2] = {{-1e30f, -1e30f}, {-1e30f, -1e30f}};
    float lrow[2][2] = {{0.f, 0.f}, {0.f, 0.f}};

    const int nkt = 2 * qt + 2;
    for (int kt = 0; kt < nkt; kt++) {
#pragma unroll
        for (int it = 0; it < 4; it++) {
            int lin = tid + it * 128;
            int r = lin >> 3, d8 = (lin & 7) * 8;
            size_t gb = (size_t)(b * SS + kt * 64 + r) * KVD + hk * HD + d8;
            *(uint4*)&sKH[r * ASTR + d8] = *(const uint4*)(g_Kh + gb);
            *(uint4*)&sKL[r * ASTR + d8] = *(const uint4*)(g_Kl + gb);
            *(uint4*)&sVH[r * ASTR + d8] = *(const uint4*)(g_Vh + gb);
            *(uint4*)&sVL[r * ASTR + d8] = *(const uint4*)(g_Vl + gb);
        }
        __syncthreads();

        float sS[2][8][4];
#pragma unroll
        for (int mt = 0; mt < 2; mt++)
#pragma unroll
            for (int i = 0; i < 8; i++)
#pragma unroll
                for (int c = 0; c < 4; c++) sS[mt][i][c] = 0.f;

        {
            int brow_base = (lane & 7) + ((lane >> 4) & 1) * 8;
            int bcol = ((lane >> 3) & 1) * 8;
#pragma unroll
            for (int kk = 0; kk < 4; kk++) {
                unsigned kbh[4][4], kbl[4][4];
#pragma unroll
                for (int ntp = 0; ntp < 4; ntp++) {
                    ldmx4(kbh[ntp], &sKH[(ntp * 16 + brow_base) * ASTR + kk * 16 + bcol]);
                    ldmx4(kbl[ntp], &sKL[(ntp * 16 + brow_base) * ASTR + kk * 16 + bcol]);
                }
                // pass 1: all hi (16 MMAs distinct accs)
#pragma unroll
                for (int ntp = 0; ntp < 4; ntp++)
#pragma unroll
                    for (int mt = 0; mt < 2; mt++) {
                        mma_f16(sS[mt][2 * ntp],     qh[mt][kk], kbh[ntp]);
                        mma_f16(sS[mt][2 * ntp + 1], qh[mt][kk], kbh[ntp] + 2);
                    }
                // pass 2: all lo
#pragma unroll
                for (int ntp = 0; ntp < 4; ntp++)
#pragma unroll
                    for (int mt = 0; mt < 2; mt++) {
                        mma_f16(sS[mt][2 * ntp],     qh[mt][kk], kbl[ntp]);
                        mma_f16(sS[mt][2 * ntp + 1], qh[mt][kk], kbl[ntp] + 2);
                    }
            }
        }

        if (kt >= 2 * qt) {
#pragma unroll
            for (int mt = 0; mt < 2; mt++)
#pragma unroll
                for (int nt = 0; nt < 8; nt++)
#pragma unroll
                    for (int c = 0; c < 4; c++) {
                        int colg = kt * 64 + nt * 8 + 2 * tg + (c & 1);
                        int rowg = q0 + m0 + mt * 16 + g + ((c >> 1) & 1) * 8;
                        if (colg > rowg) sS[mt][nt][c] = -1e30f;
                    }
        }

        float corr[2][2];
#pragma unroll
        for (int mt = 0; mt < 2; mt++)
#pragma unroll
            for (int rr = 0; rr < 2; rr++) {
                float mx = -1e30f;
#pragma unroll
                for (int nt = 0; nt < 8; nt++)
                    mx = fmaxf(mx, fmaxf(sS[mt][nt][2 * rr], sS[mt][nt][2 * rr + 1]));
                mx = fmaxf(mx, __shfl_xor_sync(0xffffffffu, mx, 1));
                mx = fmaxf(mx, __shfl_xor_sync(0xffffffffu, mx, 2));
                float mn = fmaxf(mrow[mt][rr], mx);
                corr[mt][rr] = __expf(mrow[mt][rr] - mn);
                float lt = 0.f;
#pragma unroll
                for (int nt = 0; nt < 8; nt++) {
                    float e0 = __expf(sS[mt][nt][2 * rr]     - mn);
                    float e1 = __expf(sS[mt][nt][2 * rr + 1] - mn);
                    sS[mt][nt][2 * rr] = e0; sS[mt][nt][2 * rr + 1] = e1;
                    lt += e0 + e1;
                }
                lt += __shfl_xor_sync(0xffffffffu, lt, 1);
                lt += __shfl_xor_sync(0xffffffffu, lt, 2);
                lrow[mt][rr] = lrow[mt][rr] * corr[mt][rr] + lt;
                mrow[mt][rr] = mn;
            }
#pragma unroll
        for (int mt = 0; mt < 2; mt++)
#pragma unroll
            for (int nt = 0; nt < 8; nt++) {
                oO[mt][nt][0] *= corr[mt][0]; oO[mt][nt][1] *= corr[mt][0];
                oO[mt][nt][2] *= corr[mt][1]; oO[mt][nt][3] *= corr[mt][1];
            }

        // O += P V
        {
            int vrow_base = (lane & 15);
            int vcol = (lane >> 4) * 8;
#pragma unroll
            for (int kk2 = 0; kk2 < 4; kk2++) {
                unsigned aPh[2][4];
#pragma unroll
                for (int mt = 0; mt < 2; mt++)
#pragma unroll
                    for (int half = 0; half < 2; half++) {
                        int nt = 2 * kk2 + half;
                        aPh[mt][2 * half] = pkh(__float2half(sS[mt][nt][0]),
                                                __float2half(sS[mt][nt][1]));
                        aPh[mt][2 * half + 1] = pkh(__float2half(sS[mt][nt][2]),
                                                    __float2half(sS[mt][nt][3]));
                    }
                unsigned vbh[4][4], vbl[4][4];
#pragma unroll
                for (int dtp = 0; dtp < 4; dtp++) {
                    ldmx4t(vbh[dtp], &sVH[(kk2 * 16 + vrow_base) * ASTR + dtp * 16 + vcol]);
                    ldmx4t(vbl[dtp], &sVL[(kk2 * 16 + vrow_base) * ASTR + dtp * 16 + vcol]);
                }
                // pass 1: all hi
#pragma unroll
                for (int dtp = 0; dtp < 4; dtp++)
#pragma unroll
                    for (int mt = 0; mt < 2; mt++) {
                        mma_f16(oO[mt][2 * dtp],     aPh[mt], vbh[dtp]);
                        mma_f16(oO[mt][2 * dtp + 1], aPh[mt], vbh[dtp] + 2);
                    }
                // pass 2: all lo
#pragma unroll
                for (int dtp = 0; dtp < 4; dtp++)
#pragma unroll
                    for (int mt = 0; mt < 2; mt++) {
                        mma_f16(oO[mt][2 * dtp],     aPh[mt], vbl[dtp]);
                        mma_f16(oO[mt][2 * dtp + 1], aPh[mt], vbl[dtp] + 2);
                    }
            }
        }
        __syncthreads();
    }

    // epilogue: hi-only store to g_Ah
#pragma unroll
    for (int mt = 0; mt < 2; mt++) {
        float inv0 = 1.0f / lrow[mt][0];
        float inv1 = 1.0f / lrow[mt][1];
#pragma unroll
        for (int nt = 0; nt < 8; nt++) {
            int col = h * HD + nt * 8 + 2 * tg;
            size_t off0 = (size_t)(b * SS + q0 + m0 + mt * 16 + g) * DD + col;
            size_t off1 = off0 + (size_t)8 * DD;
            *(unsigned*)(g_Ah + off0) = pkh(__float2half(oO[mt][nt][0] * inv0),
                                            __float2half(oO[mt][nt][1] * inv0));
            *(unsigned*)(g_Ah + off1) = pkh(__float2half(oO[mt][nt][2] * inv1),
                                            __float2half(oO[mt][nt][3] * inv1));
        }
    }
}

// ---------------------------------------------------------------------------
extern "C" void kernel_launch(void* const* d_in, const int* in_sizes, int n_in,
                              void* d_out, int out_size)
{
    const float* x   = (const float*)d_in[0];
    const float* fco = (const float*)d_in[1];
    const float* fsi = (const float*)d_in[2];
    const float* wq  = (const float*)d_in[3];
    const float* wk  = (const float*)d_in[4];
    const float* wv  = (const float*)d_in[5];
    const float* wo  = (const float*)d_in[6];
    float* out = (float*)d_out;

    cudaFuncSetAttribute(gemm_mma, cudaFuncAttributeMaxDynamicSharedMemorySize, GEMM_SMEM);

    cvt_kernel<<<(BS * DD + 255) / 256, 256>>>(x, BS * DD);
    wtr_kernel<<<dim3(NQKV / 32, DD / 32), dim3(32, 8)>>>(wq, wk, wv, 0);
    wtr_kernel<<<dim3(DD / 32, DD / 32), dim3(32, 8)>>>(wo, wo, wo, 1);

    // merged QKV projection with fused RoPE epilogue
    gemm_mma<<<dim3(NQKV / 128, BS / 128), 128, GEMM_SMEM>>>(0, 0, nullptr, 0, fco, fsi);

    // attention (128 q-rows per CTA)
    attn_mma_kernel<<<dim3(SS / 128, NH, BB), 128>>>();

    // output projection (fp32 epilogue -> out)
    gemm_mma<<<dim3(DD / 128, BS / 128), 128, GEMM_SMEM>>>(1, 1, out, 1, fco, fsi);
}